// round 9
// baseline (speedup 1.0000x reference)
#include <cuda_runtime.h>
#include <cuda_bf16.h>
#include <cstdint>

typedef unsigned long long u64;

#define B_SZ   1024
#define T_SZ   256
#define F_SZ   256
#define H_SZ   64
#define G4H    256

// ---------------------------------------------------------------------------
// Scratch (device globals)
// ---------------------------------------------------------------------------
__device__ float g_xw0[(size_t)T_SZ * B_SZ * G4H];   // [T,B,4H]
__device__ float g_hout[(size_t)B_SZ * H_SZ];
__device__ float g_mean[H_SZ];
__device__ float g_rstd[H_SZ];

// ---------------------------------------------------------------------------
// helpers
// ---------------------------------------------------------------------------
__device__ __forceinline__ float sigf(float x) {
    return __fdividef(1.f, 1.f + __expf(-x));
}
__device__ __forceinline__ float tanhfast(float x) {
    return 2.f * __fdividef(1.f, 1.f + __expf(-2.f * x)) - 1.f;
}

// bf16 hi/lo split: x = hi + lo with ~16 effective mantissa bits
__device__ __forceinline__ void cvt_hilo(float x, float y, uint32_t& hi, uint32_t& lo) {
    __nv_bfloat162 h = __floats2bfloat162_rn(x, y);
    float rx = x - __bfloat162float(h.x);
    float ry = y - __bfloat162float(h.y);
    __nv_bfloat162 l = __floats2bfloat162_rn(rx, ry);
    hi = *(uint32_t*)&h;
    lo = *(uint32_t*)&l;
}

// m16n8k16 row.col bf16 MMA, f32 accum
__device__ __forceinline__ void mma16816(float* c, const uint32_t* a, uint32_t b0, uint32_t b1) {
    asm volatile(
        "mma.sync.aligned.m16n8k16.row.col.f32.bf16.bf16.f32 "
        "{%0,%1,%2,%3}, {%4,%5,%6,%7}, {%8,%9}, {%0,%1,%2,%3};\n"
        : "+f"(c[0]), "+f"(c[1]), "+f"(c[2]), "+f"(c[3])
        : "r"(a[0]), "r"(a[1]), "r"(a[2]), "r"(a[3]), "r"(b0), "r"(b1));
}

// ---------------------------------------------------------------------------
// Kernel 1: input projection GEMM via bf16 tensor cores (hi/lo, 3 MMAs)
// (validated in R7 bench; unchanged)
// ---------------------------------------------------------------------------
#define AS_STR 132
#define GEMM_SMEM_U32 (2*128*AS_STR + 2*64*AS_STR + 256)

__global__ __launch_bounds__(256) void input_gemm(
    const float* __restrict__ x,
    const float* __restrict__ Wih0,
    const float* __restrict__ bih0,
    const float* __restrict__ bhh0,
    float* __restrict__ xw0)
{
    extern __shared__ uint32_t smu[];
    uint32_t* As_hi = smu;
    uint32_t* As_lo = As_hi + 128 * AS_STR;
    uint32_t* Bs_hi = As_lo + 128 * AS_STR;
    uint32_t* Bs_lo = Bs_hi + 64 * AS_STR;
    float*    sbias = (float*)(Bs_lo + 64 * AS_STR);

    const int tid  = threadIdx.x;
    const int lane = tid & 31;
    const int wid  = tid >> 5;
    const int wm   = wid & 3;
    const int wn   = wid >> 2;
    const int g    = lane >> 2;
    const int t4   = lane & 3;
    const int m0   = blockIdx.x * 128;
    const int tt   = m0 >> 10;

    sbias[tid] = bih0[tid] + bhh0[tid];

    {
        int row = tid >> 1, half = tid & 1;
        int b   = (m0 + row) & 1023;
        const float4* src = (const float4*)(x + ((size_t)b * T_SZ + tt) * F_SZ + half * 128);
        uint32_t* dhi = As_hi + row * AS_STR + half * 64;
        uint32_t* dlo = As_lo + row * AS_STR + half * 64;
#pragma unroll 8
        for (int q = 0; q < 32; q++) {
            float4 v = src[q];
            cvt_hilo(v.x, v.y, dhi[2 * q],     dlo[2 * q]);
            cvt_hilo(v.z, v.w, dhi[2 * q + 1], dlo[2 * q + 1]);
        }
    }

    for (int nc = 0; nc < 4; nc++) {
        const int n0 = nc * 64;
        {
            int row = tid >> 2, q4 = tid & 3;
            const float4* src = (const float4*)(Wih0 + (size_t)(n0 + row) * F_SZ + q4 * 64);
            uint32_t* dhi = Bs_hi + row * AS_STR + q4 * 32;
            uint32_t* dlo = Bs_lo + row * AS_STR + q4 * 32;
#pragma unroll 8
            for (int q = 0; q < 16; q++) {
                float4 v = src[q];
                cvt_hilo(v.x, v.y, dhi[2 * q],     dlo[2 * q]);
                cvt_hilo(v.z, v.w, dhi[2 * q + 1], dlo[2 * q + 1]);
            }
        }
        __syncthreads();

        float acc[2][4][4];
#pragma unroll
        for (int mi = 0; mi < 2; mi++)
#pragma unroll
            for (int ni = 0; ni < 4; ni++)
#pragma unroll
                for (int q = 0; q < 4; q++) acc[mi][ni][q] = 0.f;

#pragma unroll 4
        for (int ks = 0; ks < 16; ks++) {
            uint32_t ah[2][4], al[2][4];
#pragma unroll
            for (int mi = 0; mi < 2; mi++) {
                const uint32_t* ph = As_hi + (wm * 32 + mi * 16 + g) * AS_STR + ks * 8 + t4;
                const uint32_t* pl = As_lo + (wm * 32 + mi * 16 + g) * AS_STR + ks * 8 + t4;
                ah[mi][0] = ph[0];            ah[mi][2] = ph[4];
                ah[mi][1] = ph[8 * AS_STR];   ah[mi][3] = ph[8 * AS_STR + 4];
                al[mi][0] = pl[0];            al[mi][2] = pl[4];
                al[mi][1] = pl[8 * AS_STR];   al[mi][3] = pl[8 * AS_STR + 4];
            }
#pragma unroll
            for (int ni = 0; ni < 4; ni++) {
                int n = wn * 32 + ni * 8 + g;
                uint32_t bh0 = Bs_hi[n * AS_STR + ks * 8 + t4];
                uint32_t bh1 = Bs_hi[n * AS_STR + ks * 8 + t4 + 4];
                uint32_t bl0 = Bs_lo[n * AS_STR + ks * 8 + t4];
                uint32_t bl1 = Bs_lo[n * AS_STR + ks * 8 + t4 + 4];
#pragma unroll
                for (int mi = 0; mi < 2; mi++) {
                    mma16816(acc[mi][ni], ah[mi], bh0, bh1);
                    mma16816(acc[mi][ni], al[mi], bh0, bh1);
                    mma16816(acc[mi][ni], ah[mi], bl0, bl1);
                }
            }
        }

#pragma unroll
        for (int mi = 0; mi < 2; mi++) {
#pragma unroll
            for (int ni = 0; ni < 4; ni++) {
                int r  = wm * 32 + mi * 16 + g;
                int cl = n0 + wn * 32 + ni * 8 + 2 * t4;
                size_t m = (size_t)(m0 + r);
                xw0[m * G4H + cl]           = acc[mi][ni][0] + sbias[cl];
                xw0[m * G4H + cl + 1]       = acc[mi][ni][1] + sbias[cl + 1];
                xw0[(m + 8) * G4H + cl]     = acc[mi][ni][2] + sbias[cl];
                xw0[(m + 8) * G4H + cl + 1] = acc[mi][ni][3] + sbias[cl + 1];
            }
        }
        __syncthreads();
    }
}

// ---------------------------------------------------------------------------
// Kernel 2: fused 2-layer LSTM recurrence on TENSOR CORES (bf16 hi/lo).
// 64 blocks x 16 batch rows. 256 threads = 8 warps; warp w owns gates
// [32w, 32w+32). Weights pre-converted once into XOR-swizzled B-fragment
// layout in smem. h state kept as bf16x2 hi/lo A-fragments; z exchanged
// through smem; c-state in registers.
// ---------------------------------------------------------------------------
#define LROWS 16
#define LSTM2_SMEM_U32 55872

__global__ __launch_bounds__(256) void lstm_mma(
    const float* __restrict__ xw0,
    const float* __restrict__ Whh0,
    const float* __restrict__ Wih1,
    const float* __restrict__ Whh1,
    const float* __restrict__ bih1,
    const float* __restrict__ bhh1,
    float* __restrict__ hout)
{
    extern __shared__ uint32_t su[];
    uint32_t* W0hi = su;
    uint32_t* W0lo = su + 8192;
    uint32_t* W1hi = su + 16384;
    uint32_t* W1lo = su + 24576;
    uint32_t* W2hi = su + 32768;
    uint32_t* W2lo = su + 40960;
    uint32_t* h0hi = su + 49152;          // [16][36]
    uint32_t* h0lo = su + 49152 + 576;
    uint32_t* h1hi = su + 49152 + 1152;
    uint32_t* h1lo = su + 49152 + 1728;
    float*    zbuf = (float*)(su + 51456);   // [16][260]
    float*    sbias = (float*)(su + 55616);  // [256]

    const int tid  = threadIdx.x;
    const int lane = tid & 31;
    const int w    = tid >> 5;       // warp 0..7
    const int g    = lane >> 2;      // 0..7
    const int t4   = lane & 3;
    const int b0   = blockIdx.x * LROWS;

    // ---- one-time weight conversion to swizzled B-fragment layout ----
    {
        const float* Wsrc[3] = {Whh0, Wih1, Whh1};
#pragma unroll
        for (int m = 0; m < 3; m++) {
            uint32_t* dhi = su + m * 16384;
            uint32_t* dlo = dhi + 8192;
            for (int p = tid; p < 8192; p += 256) {
                int n = p >> 5, kp = p & 31;
                float w0v = Wsrc[m][n * 64 + 2 * kp];
                float w1v = Wsrc[m][n * 64 + 2 * kp + 1];
                uint32_t hi, lo;
                cvt_hilo(w0v, w1v, hi, lo);
                int col = kp ^ ((n & 7) << 2);
                dhi[n * 32 + col] = hi;
                dlo[n * 32 + col] = lo;
            }
        }
    }
    sbias[tid] = bih1[tid] + bhh1[tid];
    for (int i = tid; i < 2304; i += 256) su[49152 + i] = 0;   // zero h state
    __syncthreads();

    float2 bz[4];
#pragma unroll
    for (int gi = 0; gi < 4; gi++)
        bz[gi] = *(const float2*)&sbias[gi * 64 + 2 * lane];

    float c0[2][2] = {{0.f,0.f},{0.f,0.f}};
    float c1[2][2] = {{0.f,0.f},{0.f,0.f}};

    for (int t = 0; t < T_SZ; t++) {
        // ---- prefetch x projections for layer-0 gate phase ----
        float2 xq[2][4];
        {
            size_t toff = (size_t)t * ((size_t)B_SZ * G4H);
#pragma unroll
            for (int q = 0; q < 2; q++) {
                const float* xr = xw0 + toff + (size_t)(b0 + q * 8 + w) * G4H + 2 * lane;
#pragma unroll
                for (int gi = 0; gi < 4; gi++)
                    xq[q][gi] = *(const float2*)(xr + gi * 64);
            }
        }

        // ---- layer 0 MMA: z0 = Whh0 @ h0 ----
        float acc[4][4];
#pragma unroll
        for (int ntl = 0; ntl < 4; ntl++)
#pragma unroll
            for (int q = 0; q < 4; q++) acc[ntl][q] = 0.f;

#pragma unroll
        for (int kt = 0; kt < 4; kt++) {
            uint32_t ah[4], al[4];
            {
                const uint32_t* p0 = h0hi + g * 36 + kt * 8 + t4;
                const uint32_t* p1 = h0lo + g * 36 + kt * 8 + t4;
                ah[0] = p0[0]; ah[1] = p0[288]; ah[2] = p0[4]; ah[3] = p0[292];
                al[0] = p1[0]; al[1] = p1[288]; al[2] = p1[4]; al[3] = p1[292];
            }
            const int cA = (kt * 8 + t4) ^ (g << 2);
            const int cB = (kt * 8 + t4 + 4) ^ (g << 2);
#pragma unroll
            for (int ntl = 0; ntl < 4; ntl++) {
                int n = 32 * w + ntl * 8 + g;
                uint32_t bh0 = W0hi[n * 32 + cA], bh1 = W0hi[n * 32 + cB];
                uint32_t bl0 = W0lo[n * 32 + cA], bl1 = W0lo[n * 32 + cB];
                mma16816(acc[ntl], ah, bh0, bh1);
                mma16816(acc[ntl], al, bh0, bh1);
                mma16816(acc[ntl], ah, bl0, bl1);
            }
        }
#pragma unroll
        for (int ntl = 0; ntl < 4; ntl++) {
            int n = 32 * w + ntl * 8 + 2 * t4;
            *(float2*)&zbuf[g * 260 + n]       = make_float2(acc[ntl][0], acc[ntl][1]);
            *(float2*)&zbuf[(g + 8) * 260 + n] = make_float2(acc[ntl][2], acc[ntl][3]);
        }
        __syncthreads();   // B1: z0 ready, h0_old consumed

        // ---- layer 0 gates ----
#pragma unroll
        for (int q = 0; q < 2; q++) {
            int row = q * 8 + w;
            const float* zr = &zbuf[row * 260 + 2 * lane];
            float2 zi = *(const float2*)(zr);
            float2 zf = *(const float2*)(zr + 64);
            float2 zg = *(const float2*)(zr + 128);
            float2 zo = *(const float2*)(zr + 192);
            float hx, hy;
            {
                float vi = zi.x + xq[q][0].x, vf = zf.x + xq[q][1].x;
                float vg = zg.x + xq[q][2].x, vo = zo.x + xq[q][3].x;
                c0[q][0] = sigf(vf) * c0[q][0] + sigf(vi) * tanhfast(vg);
                hx = sigf(vo) * tanhfast(c0[q][0]);
            }
            {
                float vi = zi.y + xq[q][0].y, vf = zf.y + xq[q][1].y;
                float vg = zg.y + xq[q][2].y, vo = zo.y + xq[q][3].y;
                c0[q][1] = sigf(vf) * c0[q][1] + sigf(vi) * tanhfast(vg);
                hy = sigf(vo) * tanhfast(c0[q][1]);
            }
            uint32_t hi, lo;
            cvt_hilo(hx, hy, hi, lo);
            h0hi[row * 36 + lane] = hi;
            h0lo[row * 36 + lane] = lo;
        }
        __syncthreads();   // B2: h0_new ready

        // ---- layer 1 MMA: z1 = Wih1 @ h0_new + Whh1 @ h1_old ----
#pragma unroll
        for (int ntl = 0; ntl < 4; ntl++)
#pragma unroll
            for (int q = 0; q < 4; q++) acc[ntl][q] = 0.f;

#pragma unroll
        for (int src = 0; src < 2; src++) {
            const uint32_t* Ahi = src ? h1hi : h0hi;
            const uint32_t* Alo = src ? h1lo : h0lo;
            const uint32_t* Bhi = src ? W2hi : W1hi;
            const uint32_t* Blo = src ? W2lo : W1lo;
#pragma unroll
            for (int kt = 0; kt < 4; kt++) {
                uint32_t ah[4], al[4];
                {
                    const uint32_t* p0 = Ahi + g * 36 + kt * 8 + t4;
                    const uint32_t* p1 = Alo + g * 36 + kt * 8 + t4;
                    ah[0] = p0[0]; ah[1] = p0[288]; ah[2] = p0[4]; ah[3] = p0[292];
                    al[0] = p1[0]; al[1] = p1[288]; al[2] = p1[4]; al[3] = p1[292];
                }
                const int cA = (kt * 8 + t4) ^ (g << 2);
                const int cB = (kt * 8 + t4 + 4) ^ (g << 2);
#pragma unroll
                for (int ntl = 0; ntl < 4; ntl++) {
                    int n = 32 * w + ntl * 8 + g;
                    uint32_t bh0 = Bhi[n * 32 + cA], bh1 = Bhi[n * 32 + cB];
                    uint32_t bl0 = Blo[n * 32 + cA], bl1 = Blo[n * 32 + cB];
                    mma16816(acc[ntl], ah, bh0, bh1);
                    mma16816(acc[ntl], al, bh0, bh1);
                    mma16816(acc[ntl], ah, bl0, bl1);
                }
            }
        }
        __syncthreads();   // B3a (insurance)
#pragma unroll
        for (int ntl = 0; ntl < 4; ntl++) {
            int n = 32 * w + ntl * 8 + 2 * t4;
            *(float2*)&zbuf[g * 260 + n]       = make_float2(acc[ntl][0], acc[ntl][1]);
            *(float2*)&zbuf[(g + 8) * 260 + n] = make_float2(acc[ntl][2], acc[ntl][3]);
        }
        __syncthreads();   // B3: z1 ready, h1_old consumed

        // ---- layer 1 gates ----
#pragma unroll
        for (int q = 0; q < 2; q++) {
            int row = q * 8 + w;
            const float* zr = &zbuf[row * 260 + 2 * lane];
            float2 zi = *(const float2*)(zr);
            float2 zf = *(const float2*)(zr + 64);
            float2 zg = *(const float2*)(zr + 128);
            float2 zo = *(const float2*)(zr + 192);
            float hx, hy;
            {
                float vi = zi.x + bz[0].x, vf = zf.x + bz[1].x;
                float vg = zg.x + bz[2].x, vo = zo.x + bz[3].x;
                c1[q][0] = sigf(vf) * c1[q][0] + sigf(vi) * tanhfast(vg);
                hx = sigf(vo) * tanhfast(c1[q][0]);
            }
            {
                float vi = zi.y + bz[0].y, vf = zf.y + bz[1].y;
                float vg = zg.y + bz[2].y, vo = zo.y + bz[3].y;
                c1[q][1] = sigf(vf) * c1[q][1] + sigf(vi) * tanhfast(vg);
                hy = sigf(vo) * tanhfast(c1[q][1]);
            }
            uint32_t hi, lo;
            cvt_hilo(hx, hy, hi, lo);
            h1hi[row * 36 + lane] = hi;
            h1lo[row * 36 + lane] = lo;
            if (t == T_SZ - 1)
                *(float2*)&hout[(size_t)(b0 + row) * H_SZ + 2 * lane] = make_float2(hx, hy);
        }
        __syncthreads();   // B4: h1_new ready for next step
    }
}

// ---------------------------------------------------------------------------
// Kernel 3: batchnorm statistics
// ---------------------------------------------------------------------------
__global__ __launch_bounds__(256) void bn_stats(
    const float* __restrict__ h, float* __restrict__ mean, float* __restrict__ rstd)
{
    const int k = blockIdx.x;
    __shared__ float s1[256], s2[256];
    float a = 0.f, b = 0.f;
    for (int i = threadIdx.x; i < B_SZ; i += 256) {
        float v = h[(size_t)i * H_SZ + k];
        a += v; b += v * v;
    }
    s1[threadIdx.x] = a; s2[threadIdx.x] = b;
    __syncthreads();
    for (int s = 128; s > 0; s >>= 1) {
        if (threadIdx.x < s) { s1[threadIdx.x] += s1[threadIdx.x + s]; s2[threadIdx.x] += s2[threadIdx.x + s]; }
        __syncthreads();
    }
    if (threadIdx.x == 0) {
        float m = s1[0] / (float)B_SZ;
        float var = s2[0] / (float)B_SZ - m * m;
        mean[k] = m;
        rstd[k] = rsqrtf(var + 1e-5f);
    }
}

// ---------------------------------------------------------------------------
// Kernel 4: BN apply + MLP trunk + 3 heads
// ---------------------------------------------------------------------------
__global__ __launch_bounds__(256) void mlp_head(
    const float* __restrict__ hbuf,
    const float* __restrict__ mean, const float* __restrict__ rstd,
    const float* __restrict__ gamma, const float* __restrict__ beta,
    const float* __restrict__ W1, const float* __restrict__ b1,
    const float* __restrict__ W2, const float* __restrict__ b2,
    const float* __restrict__ Wmc, const float* __restrict__ bmc,
    const float* __restrict__ Wco, const float* __restrict__ bco,
    const float* __restrict__ Wip, const float* __restrict__ bip,
    float* __restrict__ out)
{
    __shared__ float sH[32][64];
    __shared__ float sY1[32][64];
    __shared__ float sY2[32][32];
    __shared__ float sW1[64 * 64];
    __shared__ float sW2[32 * 64];
    __shared__ float sWh[7 * 32];
    __shared__ float sB1[64], sB2[32], sBh[7];

    const int tid = threadIdx.x;
    const int r0  = blockIdx.x * 32;

    for (int i = tid; i < 64 * 64; i += 256) sW1[i] = W1[i];
    for (int i = tid; i < 32 * 64; i += 256) sW2[i] = W2[i];
    for (int i = tid; i < 7 * 32; i += 256)
        sWh[i] = (i < 96) ? Wmc[i] : (i < 160 ? Wco[i - 96] : Wip[i - 160]);
    if (tid < 64) sB1[tid] = b1[tid];
    if (tid < 32) sB2[tid] = b2[tid];
    if (tid < 7)  sBh[tid] = (tid < 3) ? bmc[tid] : (tid < 5 ? bco[tid - 3] : bip[tid - 5]);

    for (int i = tid; i < 32 * 64; i += 256) {
        int r = i >> 6, k = i & 63;
        float v = hbuf[(size_t)(r0 + r) * 64 + k];
        sH[r][k] = (v - mean[k]) * rstd[k] * gamma[k] + beta[k];
    }
    __syncthreads();

    for (int i = tid; i < 32 * 64; i += 256) {
        int r = i >> 6, o = i & 63;
        float a = sB1[o];
#pragma unroll
        for (int k = 0; k < 64; k++) a += sW1[o * 64 + k] * sH[r][k];
        sY1[r][o] = fmaxf(a, 0.f);
    }
    __syncthreads();

    for (int i = tid; i < 32 * 32; i += 256) {
        int r = i >> 5, o = i & 31;
        float a = sB2[o];
#pragma unroll
        for (int k = 0; k < 64; k++) a += sW2[o * 64 + k] * sY1[r][k];
        sY2[r][o] = fmaxf(a, 0.f);
    }
    __syncthreads();

    for (int i = tid; i < 32 * 7; i += 256) {
        int r = i / 7, o = i % 7;
        float a = sBh[o];
#pragma unroll
        for (int k = 0; k < 32; k++) a += sWh[o * 32 + k] * sY2[r][k];
        int row = r0 + r;
        if (o < 3)       out[(size_t)row * 3 + o] = a;
        else if (o < 5)  out[3072 + (size_t)row * 2 + (o - 3)] = a;
        else             out[5120 + (size_t)row * 2 + (o - 5)] = a;
    }
}

// ---------------------------------------------------------------------------
// Launch
// ---------------------------------------------------------------------------
extern "C" void kernel_launch(void* const* d_in, const int* in_sizes, int n_in,
                              void* d_out, int out_size)
{
    const float* x      = (const float*)d_in[0];
    const float* Wih0   = (const float*)d_in[1];
    const float* Whh0   = (const float*)d_in[2];
    const float* bih0   = (const float*)d_in[3];
    const float* bhh0   = (const float*)d_in[4];
    const float* Wih1   = (const float*)d_in[5];
    const float* Whh1   = (const float*)d_in[6];
    const float* bih1   = (const float*)d_in[7];
    const float* bhh1   = (const float*)d_in[8];
    const float* gamma  = (const float*)d_in[9];
    const float* beta   = (const float*)d_in[10];
    const float* W_fc1  = (const float*)d_in[11];
    const float* b_fc1  = (const float*)d_in[12];
    const float* W_fc2  = (const float*)d_in[13];
    const float* b_fc2  = (const float*)d_in[14];
    const float* W_mc   = (const float*)d_in[15];
    const float* b_mc   = (const float*)d_in[16];
    const float* W_co   = (const float*)d_in[17];
    const float* b_co   = (const float*)d_in[18];
    const float* W_ip   = (const float*)d_in[19];
    const float* b_ip   = (const float*)d_in[20];
    float* out = (float*)d_out;

    float* xw0;   cudaGetSymbolAddress((void**)&xw0,  g_xw0);
    float* hout;  cudaGetSymbolAddress((void**)&hout, g_hout);
    float* mean;  cudaGetSymbolAddress((void**)&mean, g_mean);
    float* rstd;  cudaGetSymbolAddress((void**)&rstd, g_rstd);

    // 1. input projection GEMM (bf16 tensor cores, hi/lo split)
    {
        size_t smem = (size_t)GEMM_SMEM_U32 * sizeof(uint32_t);
        cudaFuncSetAttribute(input_gemm, cudaFuncAttributeMaxDynamicSharedMemorySize, (int)smem);
        input_gemm<<<(T_SZ * B_SZ) / 128, 256, smem>>>(x, Wih0, bih0, bhh0, xw0);
    }

    // 2. fused 2-layer recurrence on tensor cores
    {
        size_t smem = (size_t)LSTM2_SMEM_U32 * sizeof(uint32_t);
        cudaFuncSetAttribute(lstm_mma, cudaFuncAttributeMaxDynamicSharedMemorySize, (int)smem);
        lstm_mma<<<B_SZ / LROWS, 256, smem>>>(xw0, Whh0, Wih1, Whh1, bih1, bhh1, hout);
    }

    // 3. batchnorm statistics
    bn_stats<<<H_SZ, 256>>>(hout, mean, rstd);

    // 4. BN apply + MLP + heads
    mlp_head<<<B_SZ / 32, 256>>>(hout, mean, rstd, gamma, beta,
                                 W_fc1, b_fc1, W_fc2, b_fc2,
                                 W_mc, b_mc, W_co, b_co, W_ip, b_ip, out);
}

// round 10
// speedup vs baseline: 1.3731x; 1.3731x over previous
#include <cuda_runtime.h>
#include <cuda_bf16.h>
#include <cstdint>

#define B_SZ   1024
#define T_SZ   256
#define F_SZ   256
#define H_SZ   64
#define G4H    256

// ---------------------------------------------------------------------------
// Scratch (device globals)
// ---------------------------------------------------------------------------
__device__ float    g_xw0[(size_t)T_SZ * B_SZ * G4H];   // [T,B,4H]
__device__ float    g_hout[(size_t)B_SZ * H_SZ];
__device__ float    g_mean[H_SZ];
__device__ float    g_rstd[H_SZ];
__device__ uint32_t g_wprep[4 * 2 * 64 * 128];          // Wih0 hi/lo bf16x2, GEMM-smem layout

// ---------------------------------------------------------------------------
// helpers
// ---------------------------------------------------------------------------
__device__ __forceinline__ float sigf(float x) {
    return __fdividef(1.f, 1.f + __expf(-x));
}
__device__ __forceinline__ float tanhfast(float x) {
    return 2.f * __fdividef(1.f, 1.f + __expf(-2.f * x)) - 1.f;
}

// bf16 hi/lo split: x = hi + lo with ~16 effective mantissa bits
__device__ __forceinline__ void cvt_hilo(float x, float y, uint32_t& hi, uint32_t& lo) {
    __nv_bfloat162 h = __floats2bfloat162_rn(x, y);
    float rx = x - __bfloat162float(h.x);
    float ry = y - __bfloat162float(h.y);
    __nv_bfloat162 l = __floats2bfloat162_rn(rx, ry);
    hi = *(uint32_t*)&h;
    lo = *(uint32_t*)&l;
}

// m16n8k16 row.col bf16 MMA, f32 accum
__device__ __forceinline__ void mma16816(float* c, const uint32_t* a, uint32_t b0, uint32_t b1) {
    asm volatile(
        "mma.sync.aligned.m16n8k16.row.col.f32.bf16.bf16.f32 "
        "{%0,%1,%2,%3}, {%4,%5,%6,%7}, {%8,%9}, {%0,%1,%2,%3};\n"
        : "+f"(c[0]), "+f"(c[1]), "+f"(c[2]), "+f"(c[3])
        : "r"(a[0]), "r"(a[1]), "r"(a[2]), "r"(a[3]), "r"(b0), "r"(b1));
}

// ---------------------------------------------------------------------------
// Kernel 0: pre-convert Wih0 -> hi/lo bf16x2 planes (GEMM Bs layout)
// layout: [nc][plane][row 0..63][kpair 0..127]
// ---------------------------------------------------------------------------
__global__ __launch_bounds__(256) void prep_w(
    const float* __restrict__ Wih0, uint32_t* __restrict__ wprep)
{
    int u = blockIdx.x * 256 + threadIdx.x;     // 2048 units: (n, kp-group of 16)
    int n = u >> 3, kg = u & 7;
    int nc = n >> 6, r = n & 63;
#pragma unroll
    for (int j = 0; j < 16; j++) {
        int p = kg * 16 + j;
        float2 v = *(const float2*)(Wih0 + (size_t)n * F_SZ + 2 * p);
        uint32_t hi, lo;
        cvt_hilo(v.x, v.y, hi, lo);
        wprep[((nc * 2 + 0) * 64 + r) * 128 + p] = hi;
        wprep[((nc * 2 + 1) * 64 + r) * 128 + p] = lo;
    }
}

// ---------------------------------------------------------------------------
// Kernel 1: input projection GEMM via bf16 tensor cores (hi/lo, 3 MMAs)
// B tiles copied pre-converted from g_wprep (no per-block conversion).
// ---------------------------------------------------------------------------
#define AS_STR 132
#define GEMM_SMEM_U32 (2*128*AS_STR + 2*64*AS_STR + 256)

__global__ __launch_bounds__(256) void input_gemm(
    const float* __restrict__ x,
    const uint32_t* __restrict__ wprep,
    const float* __restrict__ bih0,
    const float* __restrict__ bhh0,
    float* __restrict__ xw0)
{
    extern __shared__ uint32_t smu[];
    uint32_t* As_hi = smu;
    uint32_t* As_lo = As_hi + 128 * AS_STR;
    uint32_t* Bs_hi = As_lo + 128 * AS_STR;
    uint32_t* Bs_lo = Bs_hi + 64 * AS_STR;
    float*    sbias = (float*)(Bs_lo + 64 * AS_STR);

    const int tid  = threadIdx.x;
    const int lane = tid & 31;
    const int wid  = tid >> 5;
    const int wm   = wid & 3;
    const int wn   = wid >> 2;
    const int g    = lane >> 2;
    const int t4   = lane & 3;
    const int m0   = blockIdx.x * 128;
    const int tt   = m0 >> 10;

    sbias[tid] = bih0[tid] + bhh0[tid];

    // load + convert A: 128 rows x 256 k (each x element converted exactly once)
    {
        int row = tid >> 1, half = tid & 1;
        int b   = (m0 + row) & 1023;
        const float4* src = (const float4*)(x + ((size_t)b * T_SZ + tt) * F_SZ + half * 128);
        uint32_t* dhi = As_hi + row * AS_STR + half * 64;
        uint32_t* dlo = As_lo + row * AS_STR + half * 64;
#pragma unroll 8
        for (int q = 0; q < 32; q++) {
            float4 v = src[q];
            cvt_hilo(v.x, v.y, dhi[2 * q],     dlo[2 * q]);
            cvt_hilo(v.z, v.w, dhi[2 * q + 1], dlo[2 * q + 1]);
        }
    }

    for (int nc = 0; nc < 4; nc++) {
        const int n0 = nc * 64;
        // copy pre-converted B chunk (pure float4 copy)
        {
            int row = tid >> 2, q4 = tid & 3;
            const float4* shi = (const float4*)(wprep + ((nc * 2 + 0) * 64 + row) * 128 + q4 * 32);
            const float4* slo = (const float4*)(wprep + ((nc * 2 + 1) * 64 + row) * 128 + q4 * 32);
            float4* dhi = (float4*)(Bs_hi + row * AS_STR + q4 * 32);
            float4* dlo = (float4*)(Bs_lo + row * AS_STR + q4 * 32);
#pragma unroll
            for (int q = 0; q < 8; q++) { dhi[q] = shi[q]; dlo[q] = slo[q]; }
        }
        __syncthreads();

        float acc[2][4][4];
#pragma unroll
        for (int mi = 0; mi < 2; mi++)
#pragma unroll
            for (int ni = 0; ni < 4; ni++)
#pragma unroll
                for (int q = 0; q < 4; q++) acc[mi][ni][q] = 0.f;

#pragma unroll 4
        for (int ks = 0; ks < 16; ks++) {
            uint32_t ah[2][4], al[2][4];
#pragma unroll
            for (int mi = 0; mi < 2; mi++) {
                const uint32_t* ph = As_hi + (wm * 32 + mi * 16 + g) * AS_STR + ks * 8 + t4;
                const uint32_t* pl = As_lo + (wm * 32 + mi * 16 + g) * AS_STR + ks * 8 + t4;
                ah[mi][0] = ph[0];            ah[mi][2] = ph[4];
                ah[mi][1] = ph[8 * AS_STR];   ah[mi][3] = ph[8 * AS_STR + 4];
                al[mi][0] = pl[0];            al[mi][2] = pl[4];
                al[mi][1] = pl[8 * AS_STR];   al[mi][3] = pl[8 * AS_STR + 4];
            }
#pragma unroll
            for (int ni = 0; ni < 4; ni++) {
                int n = wn * 32 + ni * 8 + g;
                uint32_t bh0 = Bs_hi[n * AS_STR + ks * 8 + t4];
                uint32_t bh1 = Bs_hi[n * AS_STR + ks * 8 + t4 + 4];
                uint32_t bl0 = Bs_lo[n * AS_STR + ks * 8 + t4];
                uint32_t bl1 = Bs_lo[n * AS_STR + ks * 8 + t4 + 4];
#pragma unroll
                for (int mi = 0; mi < 2; mi++) {
                    mma16816(acc[mi][ni], ah[mi], bh0, bh1);
                    mma16816(acc[mi][ni], al[mi], bh0, bh1);
                    mma16816(acc[mi][ni], ah[mi], bl0, bl1);
                }
            }
        }

#pragma unroll
        for (int mi = 0; mi < 2; mi++) {
#pragma unroll
            for (int ni = 0; ni < 4; ni++) {
                int r  = wm * 32 + mi * 16 + g;
                int cl = n0 + wn * 32 + ni * 8 + 2 * t4;
                size_t m = (size_t)(m0 + r);
                xw0[m * G4H + cl]           = acc[mi][ni][0] + sbias[cl];
                xw0[m * G4H + cl + 1]       = acc[mi][ni][1] + sbias[cl + 1];
                xw0[(m + 8) * G4H + cl]     = acc[mi][ni][2] + sbias[cl];
                xw0[(m + 8) * G4H + cl + 1] = acc[mi][ni][3] + sbias[cl + 1];
            }
        }
        __syncthreads();
    }
}

// ---------------------------------------------------------------------------
// Kernel 2: fused 2-layer LSTM recurrence on tensor cores, v2.
// 128 blocks x 8 batch rows, 256 threads (8 warps; warp w owns gates
// [32w,32w+32) and batch row w in the gate phase).
// W0/W1 B-fragments live in REGISTERS (loaded once from gmem); W2 streams
// from swizzled smem. h rows 8..15 of the m16 fragment are implicit zeros.
// 4 barriers/step.
// ---------------------------------------------------------------------------
#define LROWS 8
// smem u32: W2hi 8192 | W2lo 8192 | h bufs 4*288 | zbuf 8*260 | bias 256
#define LSTM3_SMEM_U32 (16384 + 1152 + 2080 + 256)

__global__ __launch_bounds__(256, 1) void lstm_mma(
    const float* __restrict__ xw0,
    const float* __restrict__ Whh0,
    const float* __restrict__ Wih1,
    const float* __restrict__ Whh1,
    const float* __restrict__ bih1,
    const float* __restrict__ bhh1,
    float* __restrict__ hout)
{
    extern __shared__ uint32_t su[];
    uint32_t* W2hi = su;
    uint32_t* W2lo = su + 8192;
    uint32_t* h0hi = su + 16384;            // [8][36]
    uint32_t* h0lo = su + 16384 + 288;
    uint32_t* h1hi = su + 16384 + 576;
    uint32_t* h1lo = su + 16384 + 864;
    float*    zbuf = (float*)(su + 17536);  // [8][260]
    float*    sbias = (float*)(su + 19616); // [256]

    const int tid  = threadIdx.x;
    const int lane = tid & 31;
    const int w    = tid >> 5;       // warp 0..7
    const int g    = lane >> 2;      // 0..7
    const int t4   = lane & 3;
    const int b0   = blockIdx.x * LROWS;

    // ---- one-time: W2 into swizzled smem B-layout ----
    for (int p = tid; p < 8192; p += 256) {
        int n = p >> 5, kp = p & 31;
        float2 v = *(const float2*)(Whh1 + (size_t)n * 64 + 2 * kp);
        uint32_t hi, lo;
        cvt_hilo(v.x, v.y, hi, lo);
        int col = kp ^ ((n & 7) << 2);
        W2hi[n * 32 + col] = hi;
        W2lo[n * 32 + col] = lo;
    }
    sbias[tid] = bih1[tid] + bhh1[tid];
    for (int i = tid; i < 1152; i += 256) su[16384 + i] = 0;   // zero h state
    __syncthreads();

    // ---- one-time: W0/W1 B-fragments into registers ----
    // [kt][ntl][pos(b0,b1)][hi,lo]
    uint32_t w0f[4][4][2][2], w1f[4][4][2][2];
#pragma unroll
    for (int kt = 0; kt < 4; kt++)
#pragma unroll
        for (int ntl = 0; ntl < 4; ntl++) {
            int n  = 32 * w + ntl * 8 + g;
            int p0 = 8 * kt + t4;
            float2 v0 = *(const float2*)(Whh0 + (size_t)n * 64 + 2 * p0);
            float2 v1 = *(const float2*)(Whh0 + (size_t)n * 64 + 2 * (p0 + 4));
            cvt_hilo(v0.x, v0.y, w0f[kt][ntl][0][0], w0f[kt][ntl][0][1]);
            cvt_hilo(v1.x, v1.y, w0f[kt][ntl][1][0], w0f[kt][ntl][1][1]);
            float2 u0 = *(const float2*)(Wih1 + (size_t)n * 64 + 2 * p0);
            float2 u1 = *(const float2*)(Wih1 + (size_t)n * 64 + 2 * (p0 + 4));
            cvt_hilo(u0.x, u0.y, w1f[kt][ntl][0][0], w1f[kt][ntl][0][1]);
            cvt_hilo(u1.x, u1.y, w1f[kt][ntl][1][0], w1f[kt][ntl][1][1]);
        }

    float2 bz[4];
#pragma unroll
    for (int gi = 0; gi < 4; gi++)
        bz[gi] = *(const float2*)&sbias[gi * 64 + 2 * lane];

    float c0x = 0.f, c0y = 0.f, c1x = 0.f, c1y = 0.f;

    // x projections for this warp's row (t=0)
    const float* xrow = xw0 + (size_t)(b0 + w) * G4H + 2 * lane;
    float2 xq[4];
#pragma unroll
    for (int gi = 0; gi < 4; gi++) xq[gi] = *(const float2*)(xrow + gi * 64);

    for (int t = 0; t < T_SZ; t++) {
        // ---- layer 0 MMA: z0 = Whh0 @ h0 ----
        float acc[4][4];
#pragma unroll
        for (int ntl = 0; ntl < 4; ntl++)
#pragma unroll
            for (int q = 0; q < 4; q++) acc[ntl][q] = 0.f;

#pragma unroll
        for (int kt = 0; kt < 4; kt++) {
            uint32_t ah[4], al[4];
            {
                const uint32_t* p0 = h0hi + g * 36 + kt * 8 + t4;
                const uint32_t* p1 = h0lo + g * 36 + kt * 8 + t4;
                ah[0] = p0[0]; ah[1] = 0u; ah[2] = p0[4]; ah[3] = 0u;
                al[0] = p1[0]; al[1] = 0u; al[2] = p1[4]; al[3] = 0u;
            }
#pragma unroll
            for (int ntl = 0; ntl < 4; ntl++) {
                mma16816(acc[ntl], ah, w0f[kt][ntl][0][0], w0f[kt][ntl][1][0]);
                mma16816(acc[ntl], al, w0f[kt][ntl][0][0], w0f[kt][ntl][1][0]);
                mma16816(acc[ntl], ah, w0f[kt][ntl][0][1], w0f[kt][ntl][1][1]);
            }
        }
#pragma unroll
        for (int ntl = 0; ntl < 4; ntl++) {
            int n = 32 * w + ntl * 8 + 2 * t4;
            *(float2*)&zbuf[g * 260 + n] = make_float2(acc[ntl][0], acc[ntl][1]);
        }
        __syncthreads();   // B1: z0 ready, h0_old consumed

        // ---- layer 0 gates (row = w) ----
        {
            const float* zr = &zbuf[w * 260 + 2 * lane];
            float2 zi = *(const float2*)(zr);
            float2 zf = *(const float2*)(zr + 64);
            float2 zg = *(const float2*)(zr + 128);
            float2 zo = *(const float2*)(zr + 192);
            float hx, hy;
            {
                float vi = zi.x + xq[0].x, vf = zf.x + xq[1].x;
                float vg = zg.x + xq[2].x, vo = zo.x + xq[3].x;
                c0x = sigf(vf) * c0x + sigf(vi) * tanhfast(vg);
                hx = sigf(vo) * tanhfast(c0x);
            }
            {
                float vi = zi.y + xq[0].y, vf = zf.y + xq[1].y;
                float vg = zg.y + xq[2].y, vo = zo.y + xq[3].y;
                c0y = sigf(vf) * c0y + sigf(vi) * tanhfast(vg);
                hy = sigf(vo) * tanhfast(c0y);
            }
            uint32_t hi, lo;
            cvt_hilo(hx, hy, hi, lo);
            h0hi[w * 36 + lane] = hi;
            h0lo[w * 36 + lane] = lo;
        }
        // prefetch next step's x projections (consumed ~1500 cyc later)
        if (t < T_SZ - 1) {
            size_t off = (size_t)(t + 1) * ((size_t)B_SZ * G4H);
#pragma unroll
            for (int gi = 0; gi < 4; gi++) xq[gi] = *(const float2*)(xrow + off + gi * 64);
        }
        __syncthreads();   // B2: h0_new ready

        // ---- layer 1 MMA: z1 = Wih1 @ h0_new + Whh1 @ h1_old ----
#pragma unroll
        for (int ntl = 0; ntl < 4; ntl++)
#pragma unroll
            for (int q = 0; q < 4; q++) acc[ntl][q] = 0.f;

#pragma unroll
        for (int kt = 0; kt < 4; kt++) {
            uint32_t ah[4], al[4];
            {
                const uint32_t* p0 = h0hi + g * 36 + kt * 8 + t4;
                const uint32_t* p1 = h0lo + g * 36 + kt * 8 + t4;
                ah[0] = p0[0]; ah[1] = 0u; ah[2] = p0[4]; ah[3] = 0u;
                al[0] = p1[0]; al[1] = 0u; al[2] = p1[4]; al[3] = 0u;
            }
#pragma unroll
            for (int ntl = 0; ntl < 4; ntl++) {
                mma16816(acc[ntl], ah, w1f[kt][ntl][0][0], w1f[kt][ntl][1][0]);
                mma16816(acc[ntl], al, w1f[kt][ntl][0][0], w1f[kt][ntl][1][0]);
                mma16816(acc[ntl], ah, w1f[kt][ntl][0][1], w1f[kt][ntl][1][1]);
            }
        }
#pragma unroll
        for (int kt = 0; kt < 4; kt++) {
            uint32_t ah[4], al[4];
            {
                const uint32_t* p0 = h1hi + g * 36 + kt * 8 + t4;
                const uint32_t* p1 = h1lo + g * 36 + kt * 8 + t4;
                ah[0] = p0[0]; ah[1] = 0u; ah[2] = p0[4]; ah[3] = 0u;
                al[0] = p1[0]; al[1] = 0u; al[2] = p1[4]; al[3] = 0u;
            }
            const int cA = (kt * 8 + t4) ^ (g << 2);
            const int cB = (kt * 8 + t4 + 4) ^ (g << 2);
#pragma unroll
            for (int ntl = 0; ntl < 4; ntl++) {
                int n = 32 * w + ntl * 8 + g;
                uint32_t bh0 = W2hi[n * 32 + cA], bh1 = W2hi[n * 32 + cB];
                uint32_t bl0 = W2lo[n * 32 + cA], bl1 = W2lo[n * 32 + cB];
                mma16816(acc[ntl], ah, bh0, bh1);
                mma16816(acc[ntl], al, bh0, bh1);
                mma16816(acc[ntl], ah, bl0, bl1);
            }
        }
#pragma unroll
        for (int ntl = 0; ntl < 4; ntl++) {
            int n = 32 * w + ntl * 8 + 2 * t4;
            *(float2*)&zbuf[g * 260 + n] = make_float2(acc[ntl][0], acc[ntl][1]);
        }
        __syncthreads();   // B3: z1 ready, h1_old consumed

        // ---- layer 1 gates (row = w) ----
        {
            const float* zr = &zbuf[w * 260 + 2 * lane];
            float2 zi = *(const float2*)(zr);
            float2 zf = *(const float2*)(zr + 64);
            float2 zg = *(const float2*)(zr + 128);
            float2 zo = *(const float2*)(zr + 192);
            float hx, hy;
            {
                float vi = zi.x + bz[0].x, vf = zf.x + bz[1].x;
                float vg = zg.x + bz[2].x, vo = zo.x + bz[3].x;
                c1x = sigf(vf) * c1x + sigf(vi) * tanhfast(vg);
                hx = sigf(vo) * tanhfast(c1x);
            }
            {
                float vi = zi.y + bz[0].y, vf = zf.y + bz[1].y;
                float vg = zg.y + bz[2].y, vo = zo.y + bz[3].y;
                c1y = sigf(vf) * c1y + sigf(vi) * tanhfast(vg);
                hy = sigf(vo) * tanhfast(c1y);
            }
            uint32_t hi, lo;
            cvt_hilo(hx, hy, hi, lo);
            h1hi[w * 36 + lane] = hi;
            h1lo[w * 36 + lane] = lo;
            if (t == T_SZ - 1)
                *(float2*)&hout[(size_t)(b0 + w) * H_SZ + 2 * lane] = make_float2(hx, hy);
        }
        __syncthreads();   // B4: h1_new ready for next step
    }
}

// ---------------------------------------------------------------------------
// Kernel 3: batchnorm statistics
// ---------------------------------------------------------------------------
__global__ __launch_bounds__(256) void bn_stats(
    const float* __restrict__ h, float* __restrict__ mean, float* __restrict__ rstd)
{
    const int k = blockIdx.x;
    __shared__ float s1[256], s2[256];
    float a = 0.f, b = 0.f;
    for (int i = threadIdx.x; i < B_SZ; i += 256) {
        float v = h[(size_t)i * H_SZ + k];
        a += v; b += v * v;
    }
    s1[threadIdx.x] = a; s2[threadIdx.x] = b;
    __syncthreads();
    for (int s = 128; s > 0; s >>= 1) {
        if (threadIdx.x < s) { s1[threadIdx.x] += s1[threadIdx.x + s]; s2[threadIdx.x] += s2[threadIdx.x + s]; }
        __syncthreads();
    }
    if (threadIdx.x == 0) {
        float m = s1[0] / (float)B_SZ;
        float var = s2[0] / (float)B_SZ - m * m;
        mean[k] = m;
        rstd[k] = rsqrtf(var + 1e-5f);
    }
}

// ---------------------------------------------------------------------------
// Kernel 4: BN apply + MLP trunk + 3 heads
// ---------------------------------------------------------------------------
__global__ __launch_bounds__(256) void mlp_head(
    const float* __restrict__ hbuf,
    const float* __restrict__ mean, const float* __restrict__ rstd,
    const float* __restrict__ gamma, const float* __restrict__ beta,
    const float* __restrict__ W1, const float* __restrict__ b1,
    const float* __restrict__ W2, const float* __restrict__ b2,
    const float* __restrict__ Wmc, const float* __restrict__ bmc,
    const float* __restrict__ Wco, const float* __restrict__ bco,
    const float* __restrict__ Wip, const float* __restrict__ bip,
    float* __restrict__ out)
{
    __shared__ float sH[32][64];
    __shared__ float sY1[32][64];
    __shared__ float sY2[32][32];
    __shared__ float sW1[64 * 64];
    __shared__ float sW2[32 * 64];
    __shared__ float sWh[7 * 32];
    __shared__ float sB1[64], sB2[32], sBh[7];

    const int tid = threadIdx.x;
    const int r0  = blockIdx.x * 32;

    for (int i = tid; i < 64 * 64; i += 256) sW1[i] = W1[i];
    for (int i = tid; i < 32 * 64; i += 256) sW2[i] = W2[i];
    for (int i = tid; i < 7 * 32; i += 256)
        sWh[i] = (i < 96) ? Wmc[i] : (i < 160 ? Wco[i - 96] : Wip[i - 160]);
    if (tid < 64) sB1[tid] = b1[tid];
    if (tid < 32) sB2[tid] = b2[tid];
    if (tid < 7)  sBh[tid] = (tid < 3) ? bmc[tid] : (tid < 5 ? bco[tid - 3] : bip[tid - 5]);

    for (int i = tid; i < 32 * 64; i += 256) {
        int r = i >> 6, k = i & 63;
        float v = hbuf[(size_t)(r0 + r) * 64 + k];
        sH[r][k] = (v - mean[k]) * rstd[k] * gamma[k] + beta[k];
    }
    __syncthreads();

    for (int i = tid; i < 32 * 64; i += 256) {
        int r = i >> 6, o = i & 63;
        float a = sB1[o];
#pragma unroll
        for (int k = 0; k < 64; k++) a += sW1[o * 64 + k] * sH[r][k];
        sY1[r][o] = fmaxf(a, 0.f);
    }
    __syncthreads();

    for (int i = tid; i < 32 * 32; i += 256) {
        int r = i >> 5, o = i & 31;
        float a = sB2[o];
#pragma unroll
        for (int k = 0; k < 64; k++) a += sW2[o * 64 + k] * sY1[r][k];
        sY2[r][o] = fmaxf(a, 0.f);
    }
    __syncthreads();

    for (int i = tid; i < 32 * 7; i += 256) {
        int r = i / 7, o = i % 7;
        float a = sBh[o];
#pragma unroll
        for (int k = 0; k < 32; k++) a += sWh[o * 32 + k] * sY2[r][k];
        int row = r0 + r;
        if (o < 3)       out[(size_t)row * 3 + o] = a;
        else if (o < 5)  out[3072 + (size_t)row * 2 + (o - 3)] = a;
        else             out[5120 + (size_t)row * 2 + (o - 5)] = a;
    }
}

// ---------------------------------------------------------------------------
// Launch
// ---------------------------------------------------------------------------
extern "C" void kernel_launch(void* const* d_in, const int* in_sizes, int n_in,
                              void* d_out, int out_size)
{
    const float* x      = (const float*)d_in[0];
    const float* Wih0   = (const float*)d_in[1];
    const float* Whh0   = (const float*)d_in[2];
    const float* bih0   = (const float*)d_in[3];
    const float* bhh0   = (const float*)d_in[4];
    const float* Wih1   = (const float*)d_in[5];
    const float* Whh1   = (const float*)d_in[6];
    const float* bih1   = (const float*)d_in[7];
    const float* bhh1   = (const float*)d_in[8];
    const float* gamma  = (const float*)d_in[9];
    const float* beta   = (const float*)d_in[10];
    const float* W_fc1  = (const float*)d_in[11];
    const float* b_fc1  = (const float*)d_in[12];
    const float* W_fc2  = (const float*)d_in[13];
    const float* b_fc2  = (const float*)d_in[14];
    const float* W_mc   = (const float*)d_in[15];
    const float* b_mc   = (const float*)d_in[16];
    const float* W_co   = (const float*)d_in[17];
    const float* b_co   = (const float*)d_in[18];
    const float* W_ip   = (const float*)d_in[19];
    const float* b_ip   = (const float*)d_in[20];
    float* out = (float*)d_out;

    float* xw0;       cudaGetSymbolAddress((void**)&xw0,   g_xw0);
    float* hout;      cudaGetSymbolAddress((void**)&hout,  g_hout);
    float* mean;      cudaGetSymbolAddress((void**)&mean,  g_mean);
    float* rstd;      cudaGetSymbolAddress((void**)&rstd,  g_rstd);
    uint32_t* wprep;  cudaGetSymbolAddress((void**)&wprep, g_wprep);

    // 0. pre-convert Wih0 -> hi/lo bf16x2 (GEMM B layout)
    prep_w<<<8, 256>>>(Wih0, wprep);

    // 1. input projection GEMM (bf16 tensor cores, hi/lo split)
    {
        size_t smem = (size_t)GEMM_SMEM_U32 * sizeof(uint32_t);
        cudaFuncSetAttribute(input_gemm, cudaFuncAttributeMaxDynamicSharedMemorySize, (int)smem);
        input_gemm<<<(T_SZ * B_SZ) / 128, 256, smem>>>(x, wprep, bih0, bhh0, xw0);
    }

    // 2. fused 2-layer recurrence on tensor cores (8 rows/block, reg weights)
    {
        size_t smem = (size_t)LSTM3_SMEM_U32 * sizeof(uint32_t);
        cudaFuncSetAttribute(lstm_mma, cudaFuncAttributeMaxDynamicSharedMemorySize, (int)smem);
        lstm_mma<<<B_SZ / LROWS, 256, smem>>>(xw0, Whh0, Wih1, Whh1, bih1, bhh1, hout);
    }

    // 3. batchnorm statistics
    bn_stats<<<H_SZ, 256>>>(hout, mean, rstd);

    // 4. BN apply + MLP + heads
    mlp_head<<<B_SZ / 32, 256>>>(hout, mean, rstd, gamma, beta,
                                 W_fc1, b_fc1, W_fc2, b_fc2,
                                 W_mc, b_mc, W_co, b_co, W_ip, b_ip, out);
}

// round 12
// speedup vs baseline: 1.4080x; 1.0254x over previous
#include <cuda_runtime.h>
#include <cuda_bf16.h>
#include <cstdint>

#define B_SZ   1024
#define T_SZ   256
#define F_SZ   256
#define H_SZ   64
#define G4H    256

// ---------------------------------------------------------------------------
// Scratch (device globals)
// ---------------------------------------------------------------------------
__device__ float    g_xw0[(size_t)T_SZ * B_SZ * G4H];   // [T,B,4H]
__device__ float    g_hout[(size_t)B_SZ * H_SZ];
__device__ float    g_mean[H_SZ];
__device__ float    g_rstd[H_SZ];
__device__ uint32_t g_wprep[4 * 2 * 64 * 128];          // Wih0 hi/lo bf16x2, GEMM-smem layout

// ---------------------------------------------------------------------------
// helpers
// ---------------------------------------------------------------------------
__device__ __forceinline__ float sigf(float x) {
    return __fdividef(1.f, 1.f + __expf(-x));
}
__device__ __forceinline__ float tanhfast(float x) {
    return 2.f * __fdividef(1.f, 1.f + __expf(-2.f * x)) - 1.f;
}

// bf16 hi/lo split: x = hi + lo with ~16 effective mantissa bits
__device__ __forceinline__ void cvt_hilo(float x, float y, uint32_t& hi, uint32_t& lo) {
    __nv_bfloat162 h = __floats2bfloat162_rn(x, y);
    float rx = x - __bfloat162float(h.x);
    float ry = y - __bfloat162float(h.y);
    __nv_bfloat162 l = __floats2bfloat162_rn(rx, ry);
    hi = *(uint32_t*)&h;
    lo = *(uint32_t*)&l;
}

// m16n8k16 row.col bf16 MMA, f32 accum
__device__ __forceinline__ void mma16816(float* c, const uint32_t* a, uint32_t b0, uint32_t b1) {
    asm volatile(
        "mma.sync.aligned.m16n8k16.row.col.f32.bf16.bf16.f32 "
        "{%0,%1,%2,%3}, {%4,%5,%6,%7}, {%8,%9}, {%0,%1,%2,%3};\n"
        : "+f"(c[0]), "+f"(c[1]), "+f"(c[2]), "+f"(c[3])
        : "r"(a[0]), "r"(a[1]), "r"(a[2]), "r"(a[3]), "r"(b0), "r"(b1));
}

// ---------------------------------------------------------------------------
// Kernel 0: pre-convert Wih0 -> hi/lo bf16x2 planes (GEMM Bs layout)
// ---------------------------------------------------------------------------
__global__ __launch_bounds__(256) void prep_w(
    const float* __restrict__ Wih0, uint32_t* __restrict__ wprep)
{
    int u = blockIdx.x * 256 + threadIdx.x;
    int n = u >> 3, kg = u & 7;
    int nc = n >> 6, r = n & 63;
#pragma unroll
    for (int j = 0; j < 16; j++) {
        int p = kg * 16 + j;
        float2 v = *(const float2*)(Wih0 + (size_t)n * F_SZ + 2 * p);
        uint32_t hi, lo;
        cvt_hilo(v.x, v.y, hi, lo);
        wprep[((nc * 2 + 0) * 64 + r) * 128 + p] = hi;
        wprep[((nc * 2 + 1) * 64 + r) * 128 + p] = lo;
    }
}

// ---------------------------------------------------------------------------
// Kernel 1: input projection GEMM via bf16 tensor cores (hi/lo, 3 MMAs)
// ---------------------------------------------------------------------------
#define AS_STR 132
#define GEMM_SMEM_U32 (2*128*AS_STR + 2*64*AS_STR + 256)

__global__ __launch_bounds__(256) void input_gemm(
    const float* __restrict__ x,
    const uint32_t* __restrict__ wprep,
    const float* __restrict__ bih0,
    const float* __restrict__ bhh0,
    float* __restrict__ xw0)
{
    extern __shared__ uint32_t smu[];
    uint32_t* As_hi = smu;
    uint32_t* As_lo = As_hi + 128 * AS_STR;
    uint32_t* Bs_hi = As_lo + 128 * AS_STR;
    uint32_t* Bs_lo = Bs_hi + 64 * AS_STR;
    float*    sbias = (float*)(Bs_lo + 64 * AS_STR);

    const int tid  = threadIdx.x;
    const int lane = tid & 31;
    const int wid  = tid >> 5;
    const int wm   = wid & 3;
    const int wn   = wid >> 2;
    const int g    = lane >> 2;
    const int t4   = lane & 3;
    const int m0   = blockIdx.x * 128;
    const int tt   = m0 >> 10;

    sbias[tid] = bih0[tid] + bhh0[tid];

    {
        int row = tid >> 1, half = tid & 1;
        int b   = (m0 + row) & 1023;
        const float4* src = (const float4*)(x + ((size_t)b * T_SZ + tt) * F_SZ + half * 128);
        uint32_t* dhi = As_hi + row * AS_STR + half * 64;
        uint32_t* dlo = As_lo + row * AS_STR + half * 64;
#pragma unroll 8
        for (int q = 0; q < 32; q++) {
            float4 v = src[q];
            cvt_hilo(v.x, v.y, dhi[2 * q],     dlo[2 * q]);
            cvt_hilo(v.z, v.w, dhi[2 * q + 1], dlo[2 * q + 1]);
        }
    }

    for (int nc = 0; nc < 4; nc++) {
        const int n0 = nc * 64;
        {
            int row = tid >> 2, q4 = tid & 3;
            const float4* shi = (const float4*)(wprep + ((nc * 2 + 0) * 64 + row) * 128 + q4 * 32);
            const float4* slo = (const float4*)(wprep + ((nc * 2 + 1) * 64 + row) * 128 + q4 * 32);
            float4* dhi = (float4*)(Bs_hi + row * AS_STR + q4 * 32);
            float4* dlo = (float4*)(Bs_lo + row * AS_STR + q4 * 32);
#pragma unroll
            for (int q = 0; q < 8; q++) { dhi[q] = shi[q]; dlo[q] = slo[q]; }
        }
        __syncthreads();

        float acc[2][4][4];
#pragma unroll
        for (int mi = 0; mi < 2; mi++)
#pragma unroll
            for (int ni = 0; ni < 4; ni++)
#pragma unroll
                for (int q = 0; q < 4; q++) acc[mi][ni][q] = 0.f;

#pragma unroll 4
        for (int ks = 0; ks < 16; ks++) {
            uint32_t ah[2][4], al[2][4];
#pragma unroll
            for (int mi = 0; mi < 2; mi++) {
                const uint32_t* ph = As_hi + (wm * 32 + mi * 16 + g) * AS_STR + ks * 8 + t4;
                const uint32_t* pl = As_lo + (wm * 32 + mi * 16 + g) * AS_STR + ks * 8 + t4;
                ah[mi][0] = ph[0];            ah[mi][2] = ph[4];
                ah[mi][1] = ph[8 * AS_STR];   ah[mi][3] = ph[8 * AS_STR + 4];
                al[mi][0] = pl[0];            al[mi][2] = pl[4];
                al[mi][1] = pl[8 * AS_STR];   al[mi][3] = pl[8 * AS_STR + 4];
            }
#pragma unroll
            for (int ni = 0; ni < 4; ni++) {
                int n = wn * 32 + ni * 8 + g;
                uint32_t bh0 = Bs_hi[n * AS_STR + ks * 8 + t4];
                uint32_t bh1 = Bs_hi[n * AS_STR + ks * 8 + t4 + 4];
                uint32_t bl0 = Bs_lo[n * AS_STR + ks * 8 + t4];
                uint32_t bl1 = Bs_lo[n * AS_STR + ks * 8 + t4 + 4];
#pragma unroll
                for (int mi = 0; mi < 2; mi++) {
                    mma16816(acc[mi][ni], ah[mi], bh0, bh1);
                    mma16816(acc[mi][ni], al[mi], bh0, bh1);
                    mma16816(acc[mi][ni], ah[mi], bl0, bl1);
                }
            }
        }

#pragma unroll
        for (int mi = 0; mi < 2; mi++) {
#pragma unroll
            for (int ni = 0; ni < 4; ni++) {
                int r  = wm * 32 + mi * 16 + g;
                int cl = n0 + wn * 32 + ni * 8 + 2 * t4;
                size_t m = (size_t)(m0 + r);
                xw0[m * G4H + cl]           = acc[mi][ni][0] + sbias[cl];
                xw0[m * G4H + cl + 1]       = acc[mi][ni][1] + sbias[cl + 1];
                xw0[(m + 8) * G4H + cl]     = acc[mi][ni][2] + sbias[cl];
                xw0[(m + 8) * G4H + cl + 1] = acc[mi][ni][3] + sbias[cl + 1];
            }
        }
        __syncthreads();
    }
}

// ---------------------------------------------------------------------------
// Kernel 2: fused 2-layer LSTM recurrence on tensor cores, v3.
// 128 blocks x 8 rows. 3 barriers/step; Whh1@h1_old MMA overlapped with
// layer-0 gates (tensor + MUFU in same phase); separate z0/z1 buffers.
// ---------------------------------------------------------------------------
#define LROWS 8
#define LSTM3_SMEM_U32 (16384 + 1152 + 2*2080 + 256)

__global__ __launch_bounds__(256, 1) void lstm_mma(
    const float* __restrict__ xw0,
    const float* __restrict__ Whh0,
    const float* __restrict__ Wih1,
    const float* __restrict__ Whh1,
    const float* __restrict__ bih1,
    const float* __restrict__ bhh1,
    float* __restrict__ hout)
{
    extern __shared__ uint32_t su[];
    uint32_t* W2hi = su;
    uint32_t* W2lo = su + 8192;
    uint32_t* h0hi = su + 16384;            // [8][36]
    uint32_t* h0lo = su + 16384 + 288;
    uint32_t* h1hi = su + 16384 + 576;
    uint32_t* h1lo = su + 16384 + 864;
    float*    z0buf = (float*)(su + 17536); // [8][260]
    float*    z1buf = (float*)(su + 19616); // [8][260]
    float*    sbias = (float*)(su + 21696); // [256]

    const int tid  = threadIdx.x;
    const int lane = tid & 31;
    const int w    = tid >> 5;
    const int g    = lane >> 2;
    const int t4   = lane & 3;
    const int b0   = blockIdx.x * LROWS;

    // ---- one-time: W2 into swizzled smem B-layout ----
    for (int p = tid; p < 8192; p += 256) {
        int n = p >> 5, kp = p & 31;
        float2 v = *(const float2*)(Whh1 + (size_t)n * 64 + 2 * kp);
        uint32_t hi, lo;
        cvt_hilo(v.x, v.y, hi, lo);
        int col = kp ^ ((n & 7) << 2);
        W2hi[n * 32 + col] = hi;
        W2lo[n * 32 + col] = lo;
    }
    sbias[tid] = bih1[tid] + bhh1[tid];
    for (int i = tid; i < 1152; i += 256) su[16384 + i] = 0;

    // ---- one-time: W0/W1 B-fragments into registers ----
    uint32_t w0f[4][4][2][2], w1f[4][4][2][2];
#pragma unroll
    for (int kt = 0; kt < 4; kt++)
#pragma unroll
        for (int ntl = 0; ntl < 4; ntl++) {
            int n  = 32 * w + ntl * 8 + g;
            int p0 = 8 * kt + t4;
            float2 v0 = *(const float2*)(Whh0 + (size_t)n * 64 + 2 * p0);
            float2 v1 = *(const float2*)(Whh0 + (size_t)n * 64 + 2 * (p0 + 4));
            cvt_hilo(v0.x, v0.y, w0f[kt][ntl][0][0], w0f[kt][ntl][0][1]);
            cvt_hilo(v1.x, v1.y, w0f[kt][ntl][1][0], w0f[kt][ntl][1][1]);
            float2 u0 = *(const float2*)(Wih1 + (size_t)n * 64 + 2 * p0);
            float2 u1 = *(const float2*)(Wih1 + (size_t)n * 64 + 2 * (p0 + 4));
            cvt_hilo(u0.x, u0.y, w1f[kt][ntl][0][0], w1f[kt][ntl][0][1]);
            cvt_hilo(u1.x, u1.y, w1f[kt][ntl][1][0], w1f[kt][ntl][1][1]);
        }
    __syncthreads();

    float2 bz[4];
#pragma unroll
    for (int gi = 0; gi < 4; gi++)
        bz[gi] = *(const float2*)&sbias[gi * 64 + 2 * lane];

    float c0x = 0.f, c0y = 0.f, c1x = 0.f, c1y = 0.f;

    const float* xrow = xw0 + (size_t)(b0 + w) * G4H + 2 * lane;
    float2 xq[4];
#pragma unroll
    for (int gi = 0; gi < 4; gi++) xq[gi] = *(const float2*)(xrow + gi * 64);

    for (int t = 0; t < T_SZ; t++) {
        // ================= phase A: L0 MMA (Whh0 @ h0_old) -> z0buf =====
        float acc0[4][4];
#pragma unroll
        for (int ntl = 0; ntl < 4; ntl++)
#pragma unroll
            for (int q = 0; q < 4; q++) acc0[ntl][q] = 0.f;

#pragma unroll
        for (int kt = 0; kt < 4; kt++) {
            uint32_t ah[4], al[4];
            {
                const uint32_t* p0 = h0hi + g * 36 + kt * 8 + t4;
                const uint32_t* p1 = h0lo + g * 36 + kt * 8 + t4;
                ah[0] = p0[0]; ah[1] = 0u; ah[2] = p0[4]; ah[3] = 0u;
                al[0] = p1[0]; al[1] = 0u; al[2] = p1[4]; al[3] = 0u;
            }
#pragma unroll
            for (int ntl = 0; ntl < 4; ntl++) {
                mma16816(acc0[ntl], ah, w0f[kt][ntl][0][0], w0f[kt][ntl][1][0]);
                mma16816(acc0[ntl], al, w0f[kt][ntl][0][0], w0f[kt][ntl][1][0]);
                mma16816(acc0[ntl], ah, w0f[kt][ntl][0][1], w0f[kt][ntl][1][1]);
            }
        }
#pragma unroll
        for (int ntl = 0; ntl < 4; ntl++) {
            int n = 32 * w + ntl * 8 + 2 * t4;
            *(float2*)&z0buf[g * 260 + n] = make_float2(acc0[ntl][0], acc0[ntl][1]);
        }
        __syncthreads();   // B1: z0 ready, h0_old fully consumed

        // ======= phase B: Whh1 @ h1_old (tensor) + layer-0 gates (MUFU) ====
        float acc1[4][4];
#pragma unroll
        for (int ntl = 0; ntl < 4; ntl++)
#pragma unroll
            for (int q = 0; q < 4; q++) acc1[ntl][q] = 0.f;

#pragma unroll
        for (int kt = 0; kt < 4; kt++) {
            uint32_t ah[4], al[4];
            {
                const uint32_t* p0 = h1hi + g * 36 + kt * 8 + t4;
                const uint32_t* p1 = h1lo + g * 36 + kt * 8 + t4;
                ah[0] = p0[0]; ah[1] = 0u; ah[2] = p0[4]; ah[3] = 0u;
                al[0] = p1[0]; al[1] = 0u; al[2] = p1[4]; al[3] = 0u;
            }
            const int cA = (kt * 8 + t4) ^ (g << 2);
            const int cB = (kt * 8 + t4 + 4) ^ (g << 2);
#pragma unroll
            for (int ntl = 0; ntl < 4; ntl++) {
                int n = 32 * w + ntl * 8 + g;
                uint32_t bh0 = W2hi[n * 32 + cA], bh1 = W2hi[n * 32 + cB];
                uint32_t bl0 = W2lo[n * 32 + cA], bl1 = W2lo[n * 32 + cB];
                mma16816(acc1[ntl], ah, bh0, bh1);
                mma16816(acc1[ntl], al, bh0, bh1);
                mma16816(acc1[ntl], ah, bl0, bl1);
            }
        }

        // layer-0 gates for row w (overlaps with tensor work above)
        {
            const float* zr = &z0buf[w * 260 + 2 * lane];
            float2 zi = *(const float2*)(zr);
            float2 zf = *(const float2*)(zr + 64);
            float2 zg = *(const float2*)(zr + 128);
            float2 zo = *(const float2*)(zr + 192);
            float hx, hy;
            {
                float vi = zi.x + xq[0].x, vf = zf.x + xq[1].x;
                float vg = zg.x + xq[2].x, vo = zo.x + xq[3].x;
                c0x = sigf(vf) * c0x + sigf(vi) * tanhfast(vg);
                hx = sigf(vo) * tanhfast(c0x);
            }
            {
                float vi = zi.y + xq[0].y, vf = zf.y + xq[1].y;
                float vg = zg.y + xq[2].y, vo = zo.y + xq[3].y;
                c0y = sigf(vf) * c0y + sigf(vi) * tanhfast(vg);
                hy = sigf(vo) * tanhfast(c0y);
            }
            uint32_t hi, lo;
            cvt_hilo(hx, hy, hi, lo);
            h0hi[w * 36 + lane] = hi;
            h0lo[w * 36 + lane] = lo;
        }
        __syncthreads();   // B2: h0_new ready; h1_old consumed

        // ======= phase C: Wih1 @ h0_new (accumulate) -> z1buf ============
#pragma unroll
        for (int kt = 0; kt < 4; kt++) {
            uint32_t ah[4], al[4];
            {
                const uint32_t* p0 = h0hi + g * 36 + kt * 8 + t4;
                const uint32_t* p1 = h0lo + g * 36 + kt * 8 + t4;
                ah[0] = p0[0]; ah[1] = 0u; ah[2] = p0[4]; ah[3] = 0u;
                al[0] = p1[0]; al[1] = 0u; al[2] = p1[4]; al[3] = 0u;
            }
#pragma unroll
            for (int ntl = 0; ntl < 4; ntl++) {
                mma16816(acc1[ntl], ah, w1f[kt][ntl][0][0], w1f[kt][ntl][1][0]);
                mma16816(acc1[ntl], al, w1f[kt][ntl][0][0], w1f[kt][ntl][1][0]);
                mma16816(acc1[ntl], ah, w1f[kt][ntl][0][1], w1f[kt][ntl][1][1]);
            }
        }
#pragma unroll
        for (int ntl = 0; ntl < 4; ntl++) {
            int n = 32 * w + ntl * 8 + 2 * t4;
            *(float2*)&z1buf[g * 260 + n] = make_float2(acc1[ntl][0], acc1[ntl][1]);
        }
        __syncthreads();   // B3: z1 ready

        // ======= phase D: layer-1 gates + x prefetch (no barrier) ========
        {
            const float* zr = &z1buf[w * 260 + 2 * lane];
            float2 zi = *(const float2*)(zr);
            float2 zf = *(const float2*)(zr + 64);
            float2 zg = *(const float2*)(zr + 128);
            float2 zo = *(const float2*)(zr + 192);
            float hx, hy;
            {
                float vi = zi.x + bz[0].x, vf = zf.x + bz[1].x;
                float vg = zg.x + bz[2].x, vo = zo.x + bz[3].x;
                c1x = sigf(vf) * c1x + sigf(vi) * tanhfast(vg);
                hx = sigf(vo) * tanhfast(c1x);
            }
            {
                float vi = zi.y + bz[0].y, vf = zf.y + bz[1].y;
                float vg = zg.y + bz[2].y, vo = zo.y + bz[3].y;
                c1y = sigf(vf) * c1y + sigf(vi) * tanhfast(vg);
                hy = sigf(vo) * tanhfast(c1y);
            }
            uint32_t hi, lo;
            cvt_hilo(hx, hy, hi, lo);
            h1hi[w * 36 + lane] = hi;
            h1lo[w * 36 + lane] = lo;
            if (t == T_SZ - 1)
                *(float2*)&hout[(size_t)(b0 + w) * H_SZ + 2 * lane] = make_float2(hx, hy);
        }
        if (t < T_SZ - 1) {
            size_t off = (size_t)(t + 1) * ((size_t)B_SZ * G4H);
#pragma unroll
            for (int gi = 0; gi < 4; gi++) xq[gi] = *(const float2*)(xrow + off + gi * 64);
        }
        // no B4: next phase A touches only h0 (RAW guarded by B2+B3);
        // z0buf WAR guarded by B1+B2; h1 writes guarded by B1.
    }
}

// ---------------------------------------------------------------------------
// Kernel 3: batchnorm statistics
// ---------------------------------------------------------------------------
__global__ __launch_bounds__(256) void bn_stats(
    const float* __restrict__ h, float* __restrict__ mean, float* __restrict__ rstd)
{
    const int k = blockIdx.x;
    __shared__ float s1[256], s2[256];
    float a = 0.f, b = 0.f;
    for (int i = threadIdx.x; i < B_SZ; i += 256) {
        float v = h[(size_t)i * H_SZ + k];
        a += v; b += v * v;
    }
    s1[threadIdx.x] = a; s2[threadIdx.x] = b;
    __syncthreads();
    for (int s = 128; s > 0; s >>= 1) {
        if (threadIdx.x < s) { s1[threadIdx.x] += s1[threadIdx.x + s]; s2[threadIdx.x] += s2[threadIdx.x + s]; }
        __syncthreads();
    }
    if (threadIdx.x == 0) {
        float m = s1[0] / (float)B_SZ;
        float var = s2[0] / (float)B_SZ - m * m;
        mean[k] = m;
        rstd[k] = rsqrtf(var + 1e-5f);
    }
}

// ---------------------------------------------------------------------------
// Kernel 4: BN apply + MLP trunk + 3 heads
// ---------------------------------------------------------------------------
__global__ __launch_bounds__(256) void mlp_head(
    const float* __restrict__ hbuf,
    const float* __restrict__ mean, const float* __restrict__ rstd,
    const float* __restrict__ gamma, const float* __restrict__ beta,
    const float* __restrict__ W1, const float* __restrict__ b1,
    const float* __restrict__ W2, const float* __restrict__ b2,
    const float* __restrict__ Wmc, const float* __restrict__ bmc,
    const float* __restrict__ Wco, const float* __restrict__ bco,
    const float* __restrict__ Wip, const float* __restrict__ bip,
    float* __restrict__ out)
{
    __shared__ float sH[32][64];
    __shared__ float sY1[32][64];
    __shared__ float sY2[32][32];
    __shared__ float sW1[64 * 64];
    __shared__ float sW2[32 * 64];
    __shared__ float sWh[7 * 32];
    __shared__ float sB1[64], sB2[32], sBh[7];

    const int tid = threadIdx.x;
    const int r0  = blockIdx.x * 32;

    for (int i = tid; i < 64 * 64; i += 256) sW1[i] = W1[i];
    for (int i = tid; i < 32 * 64; i += 256) sW2[i] = W2[i];
    for (int i = tid; i < 7 * 32; i += 256)
        sWh[i] = (i < 96) ? Wmc[i] : (i < 160 ? Wco[i - 96] : Wip[i - 160]);
    if (tid < 64) sB1[tid] = b1[tid];
    if (tid < 32) sB2[tid] = b2[tid];
    if (tid < 7)  sBh[tid] = (tid < 3) ? bmc[tid] : (tid < 5 ? bco[tid - 3] : bip[tid - 5]);

    for (int i = tid; i < 32 * 64; i += 256) {
        int r = i >> 6, k = i & 63;
        float v = hbuf[(size_t)(r0 + r) * 64 + k];
        sH[r][k] = (v - mean[k]) * rstd[k] * gamma[k] + beta[k];
    }
    __syncthreads();

    for (int i = tid; i < 32 * 64; i += 256) {
        int r = i >> 6, o = i & 63;
        float a = sB1[o];
#pragma unroll
        for (int k = 0; k < 64; k++) a += sW1[o * 64 + k] * sH[r][k];
        sY1[r][o] = fmaxf(a, 0.f);
    }
    __syncthreads();

    for (int i = tid; i < 32 * 32; i += 256) {
        int r = i >> 5, o = i & 31;
        float a = sB2[o];
#pragma unroll
        for (int k = 0; k < 64; k++) a += sW2[o * 64 + k] * sY1[r][k];
        sY2[r][o] = fmaxf(a, 0.f);
    }
    __syncthreads();

    for (int i = tid; i < 32 * 7; i += 256) {
        int r = i / 7, o = i % 7;
        float a = sBh[o];
#pragma unroll
        for (int k = 0; k < 32; k++) a += sWh[o * 32 + k] * sY2[r][k];
        int row = r0 + r;
        if (o < 3)       out[(size_t)row * 3 + o] = a;
        else if (o < 5)  out[3072 + (size_t)row * 2 + (o - 3)] = a;
        else             out[5120 + (size_t)row * 2 + (o - 5)] = a;
    }
}

// ---------------------------------------------------------------------------
// Launch
// ---------------------------------------------------------------------------
extern "C" void kernel_launch(void* const* d_in, const int* in_sizes, int n_in,
                              void* d_out, int out_size)
{
    const float* x      = (const float*)d_in[0];
    const float* Wih0   = (const float*)d_in[1];
    const float* Whh0   = (const float*)d_in[2];
    const float* bih0   = (const float*)d_in[3];
    const float* bhh0   = (const float*)d_in[4];
    const float* Wih1   = (const float*)d_in[5];
    const float* Whh1   = (const float*)d_in[6];
    const float* bih1   = (const float*)d_in[7];
    const float* bhh1   = (const float*)d_in[8];
    const float* gamma  = (const float*)d_in[9];
    const float* beta   = (const float*)d_in[10];
    const float* W_fc1  = (const float*)d_in[11];
    const float* b_fc1  = (const float*)d_in[12];
    const float* W_fc2  = (const float*)d_in[13];
    const float* b_fc2  = (const float*)d_in[14];
    const float* W_mc   = (const float*)d_in[15];
    const float* b_mc   = (const float*)d_in[16];
    const float* W_co   = (const float*)d_in[17];
    const float* b_co   = (const float*)d_in[18];
    const float* W_ip   = (const float*)d_in[19];
    const float* b_ip   = (const float*)d_in[20];
    float* out = (float*)d_out;

    float* xw0;       cudaGetSymbolAddress((void**)&xw0,   g_xw0);
    float* hout;      cudaGetSymbolAddress((void**)&hout,  g_hout);
    float* mean;      cudaGetSymbolAddress((void**)&mean,  g_mean);
    float* rstd;      cudaGetSymbolAddress((void**)&rstd,  g_rstd);
    uint32_t* wprep;  cudaGetSymbolAddress((void**)&wprep, g_wprep);

    // 0. pre-convert Wih0 -> hi/lo bf16x2 (GEMM B layout)
    prep_w<<<8, 256>>>(Wih0, wprep);

    // 1. input projection GEMM (bf16 tensor cores, hi/lo split)
    {
        size_t smem = (size_t)GEMM_SMEM_U32 * sizeof(uint32_t);
        cudaFuncSetAttribute(input_gemm, cudaFuncAttributeMaxDynamicSharedMemorySize, (int)smem);
        input_gemm<<<(T_SZ * B_SZ) / 128, 256, smem>>>(x, wprep, bih0, bhh0, xw0);
    }

    // 2. fused 2-layer recurrence on tensor cores (3 barriers/step, overlapped)
    {
        size_t smem = (size_t)LSTM3_SMEM_U32 * sizeof(uint32_t);
        cudaFuncSetAttribute(lstm_mma, cudaFuncAttributeMaxDynamicSharedMemorySize, (int)smem);
        lstm_mma<<<B_SZ / LROWS, 256, smem>>>(xw0, Whh0, Wih1, Whh1, bih1, bhh1, hout);
    }

    // 3. batchnorm statistics
    bn_stats<<<H_SZ, 256>>>(hout, mean, rstd);

    // 4. BN apply + MLP + heads
    mlp_head<<<B_SZ / 32, 256>>>(hout, mean, rstd, gamma, beta,
                                 W_fc1, b_fc1, W_fc2, b_fc2,
                                 W_mc, b_mc, W_co, b_co, W_ip, b_ip, out);
}

// round 13
// speedup vs baseline: 1.7302x; 1.2288x over previous
#include <cuda_runtime.h>
#include <cuda_bf16.h>
#include <cuda_fp16.h>
#include <cstdint>

#define B_SZ   1024
#define T_SZ   256
#define F_SZ   256
#define H_SZ   64
#define G4H    256

// ---------------------------------------------------------------------------
// Scratch (device globals)
// ---------------------------------------------------------------------------
__device__ float    g_xw0[(size_t)T_SZ * B_SZ * G4H];   // [T,B,4H]
__device__ float    g_hout[(size_t)B_SZ * H_SZ];
__device__ float    g_mean[H_SZ];
__device__ float    g_rstd[H_SZ];
__device__ uint32_t g_wprep[4 * 2 * 64 * 128];          // Wih0 hi/lo f16x2, GEMM-smem layout

// ---------------------------------------------------------------------------
// helpers
// ---------------------------------------------------------------------------
__device__ __forceinline__ float sigf(float x) {
    return __fdividef(1.f, 1.f + __expf(-x));
}
__device__ __forceinline__ float tanhfast(float x) {
    return 2.f * __fdividef(1.f, 1.f + __expf(-2.f * x)) - 1.f;
}

// pack two floats to half2 (x -> low = even k)
__device__ __forceinline__ uint32_t f2h2(float x, float y) {
    __half2 h = __floats2half2_rn(x, y);
    return *(uint32_t*)&h;
}
// fp16 hi/lo split: v = hi + lo with ~22 effective mantissa bits
__device__ __forceinline__ void cvt_hilo_h(float x, float y, uint32_t& hi, uint32_t& lo) {
    __half2 h = __floats2half2_rn(x, y);
    float rx = x - __half2float(__low2half(h));
    float ry = y - __half2float(__high2half(h));
    __half2 l = __floats2half2_rn(rx, ry);
    hi = *(uint32_t*)&h;
    lo = *(uint32_t*)&l;
}

// m16n8k16 row.col fp16 MMA, f32 accum
__device__ __forceinline__ void mma16816(float* c, const uint32_t* a, uint32_t b0, uint32_t b1) {
    asm volatile(
        "mma.sync.aligned.m16n8k16.row.col.f32.f16.f16.f32 "
        "{%0,%1,%2,%3}, {%4,%5,%6,%7}, {%8,%9}, {%0,%1,%2,%3};\n"
        : "+f"(c[0]), "+f"(c[1]), "+f"(c[2]), "+f"(c[3])
        : "r"(a[0]), "r"(a[1]), "r"(a[2]), "r"(a[3]), "r"(b0), "r"(b1));
}

// ---------------------------------------------------------------------------
// Kernel 0: pre-convert Wih0 -> hi/lo f16x2 planes (GEMM Bs layout)
// layout: [nc][plane][row 0..63][kpair 0..127]
// ---------------------------------------------------------------------------
__global__ __launch_bounds__(256) void prep_w(
    const float* __restrict__ Wih0, uint32_t* __restrict__ wprep)
{
    int u = blockIdx.x * 256 + threadIdx.x;
    int n = u >> 3, kg = u & 7;
    int nc = n >> 6, r = n & 63;
#pragma unroll
    for (int j = 0; j < 16; j++) {
        int p = kg * 16 + j;
        float2 v = *(const float2*)(Wih0 + (size_t)n * F_SZ + 2 * p);
        uint32_t hi, lo;
        cvt_hilo_h(v.x, v.y, hi, lo);
        wprep[((nc * 2 + 0) * 64 + r) * 128 + p] = hi;
        wprep[((nc * 2 + 1) * 64 + r) * 128 + p] = lo;
    }
}

// ---------------------------------------------------------------------------
// Kernel 1: input projection GEMM, fp16 2-MMA scheme.
// A (x) single fp16 plane; B (Wih0) hi/lo fp16; acc += A*Bhi + A*Blo.
// ---------------------------------------------------------------------------
#define AS_STR 132
#define GEMM_SMEM_U32 (128*AS_STR + 2*64*AS_STR + 256)

__global__ __launch_bounds__(256) void input_gemm(
    const float* __restrict__ x,
    const uint32_t* __restrict__ wprep,
    const float* __restrict__ bih0,
    const float* __restrict__ bhh0,
    float* __restrict__ xw0)
{
    extern __shared__ uint32_t smu[];
    uint32_t* As    = smu;                        // [128][132] x as half2
    uint32_t* Bs_hi = As + 128 * AS_STR;          // [64][132]
    uint32_t* Bs_lo = Bs_hi + 64 * AS_STR;
    float*    sbias = (float*)(Bs_lo + 64 * AS_STR);

    const int tid  = threadIdx.x;
    const int lane = tid & 31;
    const int wid  = tid >> 5;
    const int wm   = wid & 3;
    const int wn   = wid >> 2;
    const int g    = lane >> 2;
    const int t4   = lane & 3;
    const int m0   = blockIdx.x * 128;
    const int tt   = m0 >> 10;

    sbias[tid] = bih0[tid] + bhh0[tid];

    // load + convert A: 128 rows x 256 k, single fp16 plane
    {
        int row = tid >> 1, half = tid & 1;
        int b   = (m0 + row) & 1023;
        const float4* src = (const float4*)(x + ((size_t)b * T_SZ + tt) * F_SZ + half * 128);
        uint32_t* d = As + row * AS_STR + half * 64;
#pragma unroll 8
        for (int q = 0; q < 32; q++) {
            float4 v = src[q];
            d[2 * q]     = f2h2(v.x, v.y);
            d[2 * q + 1] = f2h2(v.z, v.w);
        }
    }

    for (int nc = 0; nc < 4; nc++) {
        const int n0 = nc * 64;
        // copy pre-converted B chunk (pure float4 copy)
        {
            int row = tid >> 2, q4 = tid & 3;
            const float4* shi = (const float4*)(wprep + ((nc * 2 + 0) * 64 + row) * 128 + q4 * 32);
            const float4* slo = (const float4*)(wprep + ((nc * 2 + 1) * 64 + row) * 128 + q4 * 32);
            float4* dhi = (float4*)(Bs_hi + row * AS_STR + q4 * 32);
            float4* dlo = (float4*)(Bs_lo + row * AS_STR + q4 * 32);
#pragma unroll
            for (int q = 0; q < 8; q++) { dhi[q] = shi[q]; dlo[q] = slo[q]; }
        }
        __syncthreads();

        float acc[2][4][4];
#pragma unroll
        for (int mi = 0; mi < 2; mi++)
#pragma unroll
            for (int ni = 0; ni < 4; ni++)
#pragma unroll
                for (int q = 0; q < 4; q++) acc[mi][ni][q] = 0.f;

#pragma unroll 4
        for (int ks = 0; ks < 16; ks++) {
            uint32_t a[2][4];
#pragma unroll
            for (int mi = 0; mi < 2; mi++) {
                const uint32_t* p = As + (wm * 32 + mi * 16 + g) * AS_STR + ks * 8 + t4;
                a[mi][0] = p[0];            a[mi][2] = p[4];
                a[mi][1] = p[8 * AS_STR];   a[mi][3] = p[8 * AS_STR + 4];
            }
#pragma unroll
            for (int ni = 0; ni < 4; ni++) {
                int n = wn * 32 + ni * 8 + g;
                uint32_t bh0 = Bs_hi[n * AS_STR + ks * 8 + t4];
                uint32_t bh1 = Bs_hi[n * AS_STR + ks * 8 + t4 + 4];
                uint32_t bl0 = Bs_lo[n * AS_STR + ks * 8 + t4];
                uint32_t bl1 = Bs_lo[n * AS_STR + ks * 8 + t4 + 4];
#pragma unroll
                for (int mi = 0; mi < 2; mi++) {
                    mma16816(acc[mi][ni], a[mi], bh0, bh1);
                    mma16816(acc[mi][ni], a[mi], bl0, bl1);
                }
            }
        }

#pragma unroll
        for (int mi = 0; mi < 2; mi++) {
#pragma unroll
            for (int ni = 0; ni < 4; ni++) {
                int r  = wm * 32 + mi * 16 + g;
                int cl = n0 + wn * 32 + ni * 8 + 2 * t4;
                size_t m = (size_t)(m0 + r);
                xw0[m * G4H + cl]           = acc[mi][ni][0] + sbias[cl];
                xw0[m * G4H + cl + 1]       = acc[mi][ni][1] + sbias[cl + 1];
                xw0[(m + 8) * G4H + cl]     = acc[mi][ni][2] + sbias[cl];
                xw0[(m + 8) * G4H + cl + 1] = acc[mi][ni][3] + sbias[cl + 1];
            }
        }
        __syncthreads();
    }
}

// ---------------------------------------------------------------------------
// Kernel 2: fused 2-layer LSTM recurrence, fp16 2-MMA scheme.
// h single fp16 plane; weights hi/lo fp16 (W0/W1 in registers, W2 in smem).
// 128 blocks x 8 rows, 3 barriers/step, phase structure from R12.
// ---------------------------------------------------------------------------
#define LROWS 8
// smem u32: W2hi 8192 | W2lo 8192 | h0 288 | h1 288 | z0 2080 | z1 2080 | bias 256
#define LSTM4_SMEM_U32 (16384 + 576 + 2*2080 + 256)

__global__ __launch_bounds__(256, 1) void lstm_mma(
    const float* __restrict__ xw0,
    const float* __restrict__ Whh0,
    const float* __restrict__ Wih1,
    const float* __restrict__ Whh1,
    const float* __restrict__ bih1,
    const float* __restrict__ bhh1,
    float* __restrict__ hout)
{
    extern __shared__ uint32_t su[];
    uint32_t* W2hi = su;
    uint32_t* W2lo = su + 8192;
    uint32_t* h0s  = su + 16384;            // [8][36] half2
    uint32_t* h1s  = su + 16384 + 288;
    float*    z0buf = (float*)(su + 16960); // [8][260]
    float*    z1buf = (float*)(su + 19040); // [8][260]
    float*    sbias = (float*)(su + 21120); // [256]

    const int tid  = threadIdx.x;
    const int lane = tid & 31;
    const int w    = tid >> 5;
    const int g    = lane >> 2;
    const int t4   = lane & 3;
    const int b0   = blockIdx.x * LROWS;

    // ---- one-time: W2 hi/lo into swizzled smem B-layout ----
    for (int p = tid; p < 8192; p += 256) {
        int n = p >> 5, kp = p & 31;
        float2 v = *(const float2*)(Whh1 + (size_t)n * 64 + 2 * kp);
        uint32_t hi, lo;
        cvt_hilo_h(v.x, v.y, hi, lo);
        int col = kp ^ ((n & 7) << 2);
        W2hi[n * 32 + col] = hi;
        W2lo[n * 32 + col] = lo;
    }
    sbias[tid] = bih1[tid] + bhh1[tid];
    for (int i = tid; i < 576; i += 256) su[16384 + i] = 0;   // zero h state

    // ---- one-time: W0/W1 hi/lo B-fragments into registers ----
    // [kt][ntl][pos(b0,b1)][hi,lo]
    uint32_t w0f[4][4][2][2], w1f[4][4][2][2];
#pragma unroll
    for (int kt = 0; kt < 4; kt++)
#pragma unroll
        for (int ntl = 0; ntl < 4; ntl++) {
            int n  = 32 * w + ntl * 8 + g;
            int p0 = 8 * kt + t4;
            float2 v0 = *(const float2*)(Whh0 + (size_t)n * 64 + 2 * p0);
            float2 v1 = *(const float2*)(Whh0 + (size_t)n * 64 + 2 * (p0 + 4));
            cvt_hilo_h(v0.x, v0.y, w0f[kt][ntl][0][0], w0f[kt][ntl][0][1]);
            cvt_hilo_h(v1.x, v1.y, w0f[kt][ntl][1][0], w0f[kt][ntl][1][1]);
            float2 u0 = *(const float2*)(Wih1 + (size_t)n * 64 + 2 * p0);
            float2 u1 = *(const float2*)(Wih1 + (size_t)n * 64 + 2 * (p0 + 4));
            cvt_hilo_h(u0.x, u0.y, w1f[kt][ntl][0][0], w1f[kt][ntl][0][1]);
            cvt_hilo_h(u1.x, u1.y, w1f[kt][ntl][1][0], w1f[kt][ntl][1][1]);
        }
    __syncthreads();

    float2 bz[4];
#pragma unroll
    for (int gi = 0; gi < 4; gi++)
        bz[gi] = *(const float2*)&sbias[gi * 64 + 2 * lane];

    float c0x = 0.f, c0y = 0.f, c1x = 0.f, c1y = 0.f;

    const float* xrow = xw0 + (size_t)(b0 + w) * G4H + 2 * lane;
    float2 xq[4];
#pragma unroll
    for (int gi = 0; gi < 4; gi++) xq[gi] = *(const float2*)(xrow + gi * 64);

    for (int t = 0; t < T_SZ; t++) {
        // ================= phase A: L0 MMA (Whh0 @ h0_old) -> z0buf =====
        float acc0[4][4];
#pragma unroll
        for (int ntl = 0; ntl < 4; ntl++)
#pragma unroll
            for (int q = 0; q < 4; q++) acc0[ntl][q] = 0.f;

#pragma unroll
        for (int kt = 0; kt < 4; kt++) {
            uint32_t a[4];
            {
                const uint32_t* p = h0s + g * 36 + kt * 8 + t4;
                a[0] = p[0]; a[1] = 0u; a[2] = p[4]; a[3] = 0u;
            }
#pragma unroll
            for (int ntl = 0; ntl < 4; ntl++) {
                mma16816(acc0[ntl], a, w0f[kt][ntl][0][0], w0f[kt][ntl][1][0]);
                mma16816(acc0[ntl], a, w0f[kt][ntl][0][1], w0f[kt][ntl][1][1]);
            }
        }
#pragma unroll
        for (int ntl = 0; ntl < 4; ntl++) {
            int n = 32 * w + ntl * 8 + 2 * t4;
            *(float2*)&z0buf[g * 260 + n] = make_float2(acc0[ntl][0], acc0[ntl][1]);
        }
        __syncthreads();   // B1: z0 ready, h0_old fully consumed

        // ======= phase B: Whh1 @ h1_old (tensor) + layer-0 gates (MUFU) ====
        float acc1[4][4];
#pragma unroll
        for (int ntl = 0; ntl < 4; ntl++)
#pragma unroll
            for (int q = 0; q < 4; q++) acc1[ntl][q] = 0.f;

#pragma unroll
        for (int kt = 0; kt < 4; kt++) {
            uint32_t a[4];
            {
                const uint32_t* p = h1s + g * 36 + kt * 8 + t4;
                a[0] = p[0]; a[1] = 0u; a[2] = p[4]; a[3] = 0u;
            }
            const int cA = (kt * 8 + t4) ^ (g << 2);
            const int cB = (kt * 8 + t4 + 4) ^ (g << 2);
#pragma unroll
            for (int ntl = 0; ntl < 4; ntl++) {
                int n = 32 * w + ntl * 8 + g;
                uint32_t bh0 = W2hi[n * 32 + cA], bh1 = W2hi[n * 32 + cB];
                uint32_t bl0 = W2lo[n * 32 + cA], bl1 = W2lo[n * 32 + cB];
                mma16816(acc1[ntl], a, bh0, bh1);
                mma16816(acc1[ntl], a, bl0, bl1);
            }
        }

        // layer-0 gates for row w (overlaps with tensor work above)
        {
            const float* zr = &z0buf[w * 260 + 2 * lane];
            float2 zi = *(const float2*)(zr);
            float2 zf = *(const float2*)(zr + 64);
            float2 zg = *(const float2*)(zr + 128);
            float2 zo = *(const float2*)(zr + 192);
            float hx, hy;
            {
                float vi = zi.x + xq[0].x, vf = zf.x + xq[1].x;
                float vg = zg.x + xq[2].x, vo = zo.x + xq[3].x;
                c0x = sigf(vf) * c0x + sigf(vi) * tanhfast(vg);
                hx = sigf(vo) * tanhfast(c0x);
            }
            {
                float vi = zi.y + xq[0].y, vf = zf.y + xq[1].y;
                float vg = zg.y + xq[2].y, vo = zo.y + xq[3].y;
                c0y = sigf(vf) * c0y + sigf(vi) * tanhfast(vg);
                hy = sigf(vo) * tanhfast(c0y);
            }
            h0s[w * 36 + lane] = f2h2(hx, hy);
        }
        __syncthreads();   // B2: h0_new ready; h1_old consumed

        // ======= phase C: Wih1 @ h0_new (accumulate) -> z1buf ============
#pragma unroll
        for (int kt = 0; kt < 4; kt++) {
            uint32_t a[4];
            {
                const uint32_t* p = h0s + g * 36 + kt * 8 + t4;
                a[0] = p[0]; a[1] = 0u; a[2] = p[4]; a[3] = 0u;
            }
#pragma unroll
            for (int ntl = 0; ntl < 4; ntl++) {
                mma16816(acc1[ntl], a, w1f[kt][ntl][0][0], w1f[kt][ntl][1][0]);
                mma16816(acc1[ntl], a, w1f[kt][ntl][0][1], w1f[kt][ntl][1][1]);
            }
        }
#pragma unroll
        for (int ntl = 0; ntl < 4; ntl++) {
            int n = 32 * w + ntl * 8 + 2 * t4;
            *(float2*)&z1buf[g * 260 + n] = make_float2(acc1[ntl][0], acc1[ntl][1]);
        }
        __syncthreads();   // B3: z1 ready

        // ======= phase D: layer-1 gates + x prefetch (no barrier) ========
        {
            const float* zr = &z1buf[w * 260 + 2 * lane];
            float2 zi = *(const float2*)(zr);
            float2 zf = *(const float2*)(zr + 64);
            float2 zg = *(const float2*)(zr + 128);
            float2 zo = *(const float2*)(zr + 192);
            float hx, hy;
            {
                float vi = zi.x + bz[0].x, vf = zf.x + bz[1].x;
                float vg = zg.x + bz[2].x, vo = zo.x + bz[3].x;
                c1x = sigf(vf) * c1x + sigf(vi) * tanhfast(vg);
                hx = sigf(vo) * tanhfast(c1x);
            }
            {
                float vi = zi.y + bz[0].y, vf = zf.y + bz[1].y;
                float vg = zg.y + bz[2].y, vo = zo.y + bz[3].y;
                c1y = sigf(vf) * c1y + sigf(vi) * tanhfast(vg);
                hy = sigf(vo) * tanhfast(c1y);
            }
            h1s[w * 36 + lane] = f2h2(hx, hy);
            if (t == T_SZ - 1)
                *(float2*)&hout[(size_t)(b0 + w) * H_SZ + 2 * lane] = make_float2(hx, hy);
        }
        if (t < T_SZ - 1) {
            size_t off = (size_t)(t + 1) * ((size_t)B_SZ * G4H);
#pragma unroll
            for (int gi = 0; gi < 4; gi++) xq[gi] = *(const float2*)(xrow + off + gi * 64);
        }
        // no B4: hazards guarded by B1..B3 (audited in R11/R12)
    }
}

// ---------------------------------------------------------------------------
// Kernel 3: batchnorm statistics
// ---------------------------------------------------------------------------
__global__ __launch_bounds__(256) void bn_stats(
    const float* __restrict__ h, float* __restrict__ mean, float* __restrict__ rstd)
{
    const int k = blockIdx.x;
    __shared__ float s1[256], s2[256];
    float a = 0.f, b = 0.f;
    for (int i = threadIdx.x; i < B_SZ; i += 256) {
        float v = h[(size_t)i * H_SZ + k];
        a += v; b += v * v;
    }
    s1[threadIdx.x] = a; s2[threadIdx.x] = b;
    __syncthreads();
    for (int s = 128; s > 0; s >>= 1) {
        if (threadIdx.x < s) { s1[threadIdx.x] += s1[threadIdx.x + s]; s2[threadIdx.x] += s2[threadIdx.x + s]; }
        __syncthreads();
    }
    if (threadIdx.x == 0) {
        float m = s1[0] / (float)B_SZ;
        float var = s2[0] / (float)B_SZ - m * m;
        mean[k] = m;
        rstd[k] = rsqrtf(var + 1e-5f);
    }
}

// ---------------------------------------------------------------------------
// Kernel 4: BN apply + MLP trunk + 3 heads
// ---------------------------------------------------------------------------
__global__ __launch_bounds__(256) void mlp_head(
    const float* __restrict__ hbuf,
    const float* __restrict__ mean, const float* __restrict__ rstd,
    const float* __restrict__ gamma, const float* __restrict__ beta,
    const float* __restrict__ W1, const float* __restrict__ b1,
    const float* __restrict__ W2, const float* __restrict__ b2,
    const float* __restrict__ Wmc, const float* __restrict__ bmc,
    const float* __restrict__ Wco, const float* __restrict__ bco,
    const float* __restrict__ Wip, const float* __restrict__ bip,
    float* __restrict__ out)
{
    __shared__ float sH[32][64];
    __shared__ float sY1[32][64];
    __shared__ float sY2[32][32];
    __shared__ float sW1[64 * 64];
    __shared__ float sW2[32 * 64];
    __shared__ float sWh[7 * 32];
    __shared__ float sB1[64], sB2[32], sBh[7];

    const int tid = threadIdx.x;
    const int r0  = blockIdx.x * 32;

    for (int i = tid; i < 64 * 64; i += 256) sW1[i] = W1[i];
    for (int i = tid; i < 32 * 64; i += 256) sW2[i] = W2[i];
    for (int i = tid; i < 7 * 32; i += 256)
        sWh[i] = (i < 96) ? Wmc[i] : (i < 160 ? Wco[i - 96] : Wip[i - 160]);
    if (tid < 64) sB1[tid] = b1[tid];
    if (tid < 32) sB2[tid] = b2[tid];
    if (tid < 7)  sBh[tid] = (tid < 3) ? bmc[tid] : (tid < 5 ? bco[tid - 3] : bip[tid - 5]);

    for (int i = tid; i < 32 * 64; i += 256) {
        int r = i >> 6, k = i & 63;
        float v = hbuf[(size_t)(r0 + r) * 64 + k];
        sH[r][k] = (v - mean[k]) * rstd[k] * gamma[k] + beta[k];
    }
    __syncthreads();

    for (int i = tid; i < 32 * 64; i += 256) {
        int r = i >> 6, o = i & 63;
        float a = sB1[o];
#pragma unroll
        for (int k = 0; k < 64; k++) a += sW1[o * 64 + k] * sH[r][k];
        sY1[r][o] = fmaxf(a, 0.f);
    }
    __syncthreads();

    for (int i = tid; i < 32 * 32; i += 256) {
        int r = i >> 5, o = i & 31;
        float a = sB2[o];
#pragma unroll
        for (int k = 0; k < 64; k++) a += sW2[o * 64 + k] * sY1[r][k];
        sY2[r][o] = fmaxf(a, 0.f);
    }
    __syncthreads();

    for (int i = tid; i < 32 * 7; i += 256) {
        int r = i / 7, o = i % 7;
        float a = sBh[o];
#pragma unroll
        for (int k = 0; k < 32; k++) a += sWh[o * 32 + k] * sY2[r][k];
        int row = r0 + r;
        if (o < 3)       out[(size_t)row * 3 + o] = a;
        else if (o < 5)  out[3072 + (size_t)row * 2 + (o - 3)] = a;
        else             out[5120 + (size_t)row * 2 + (o - 5)] = a;
    }
}

// ---------------------------------------------------------------------------
// Launch
// ---------------------------------------------------------------------------
extern "C" void kernel_launch(void* const* d_in, const int* in_sizes, int n_in,
                              void* d_out, int out_size)
{
    const float* x      = (const float*)d_in[0];
    const float* Wih0   = (const float*)d_in[1];
    const float* Whh0   = (const float*)d_in[2];
    const float* bih0   = (const float*)d_in[3];
    const float* bhh0   = (const float*)d_in[4];
    const float* Wih1   = (const float*)d_in[5];
    const float* Whh1   = (const float*)d_in[6];
    const float* bih1   = (const float*)d_in[7];
    const float* bhh1   = (const float*)d_in[8];
    const float* gamma  = (const float*)d_in[9];
    const float* beta   = (const float*)d_in[10];
    const float* W_fc1  = (const float*)d_in[11];
    const float* b_fc1  = (const float*)d_in[12];
    const float* W_fc2  = (const float*)d_in[13];
    const float* b_fc2  = (const float*)d_in[14];
    const float* W_mc   = (const float*)d_in[15];
    const float* b_mc   = (const float*)d_in[16];
    const float* W_co   = (const float*)d_in[17];
    const float* b_co   = (const float*)d_in[18];
    const float* W_ip   = (const float*)d_in[19];
    const float* b_ip   = (const float*)d_in[20];
    float* out = (float*)d_out;

    float* xw0;       cudaGetSymbolAddress((void**)&xw0,   g_xw0);
    float* hout;      cudaGetSymbolAddress((void**)&hout,  g_hout);
    float* mean;      cudaGetSymbolAddress((void**)&mean,  g_mean);
    float* rstd;      cudaGetSymbolAddress((void**)&rstd,  g_rstd);
    uint32_t* wprep;  cudaGetSymbolAddress((void**)&wprep, g_wprep);

    // 0. pre-convert Wih0 -> hi/lo f16x2 (GEMM B layout)
    prep_w<<<8, 256>>>(Wih0, wprep);

    // 1. input projection GEMM (fp16 2-MMA)
    {
        size_t smem = (size_t)GEMM_SMEM_U32 * sizeof(uint32_t);
        cudaFuncSetAttribute(input_gemm, cudaFuncAttributeMaxDynamicSharedMemorySize, (int)smem);
        input_gemm<<<(T_SZ * B_SZ) / 128, 256, smem>>>(x, wprep, bih0, bhh0, xw0);
    }

    // 2. fused 2-layer recurrence (fp16 2-MMA, 3 barriers/step)
    {
        size_t smem = (size_t)LSTM4_SMEM_U32 * sizeof(uint32_t);
        cudaFuncSetAttribute(lstm_mma, cudaFuncAttributeMaxDynamicSharedMemorySize, (int)smem);
        lstm_mma<<<B_SZ / LROWS, 256, smem>>>(xw0, Whh0, Wih1, Whh1, bih1, bhh1, hout);
    }

    // 3. batchnorm statistics
    bn_stats<<<H_SZ, 256>>>(hout, mean, rstd);

    // 4. BN apply + MLP + heads
    mlp_head<<<B_SZ / 32, 256>>>(hout, mean, rstd, gamma, beta,
                                 W_fc1, b_fc1, W_fc2, b_fc2,
                                 W_mc, b_mc, W_co, b_co, W_ip, b_ip, out);
}